// round 5
// baseline (speedup 1.0000x reference)
#include <cuda_runtime.h>
#include <cuda_bf16.h>
#include <math.h>
#include <stdint.h>

#define HID   2048
#define NH    16
#define HD    128
#define BATCH 4
#define SEQ   2048
#define MROWS (BATCH*SEQ)     // 8192
#define QKVN  (3*HID)         // 6144
#define KSPLIT (3*HID)        // 6144

// ---------------------------------------------------------------------------
// Scratch
// ---------------------------------------------------------------------------
__device__ __align__(1024) __nv_bfloat16 g_ab[(size_t)MROWS * KSPLIT];
__device__ __align__(1024) __nv_bfloat16 g_bqkv[(size_t)QKVN * KSPLIT];
__device__ __align__(1024) __nv_bfloat16 g_bdense[(size_t)HID * KSPLIT];
// per-head split layout: [sel(q,k,v)][b][h][s][hi128|lo128]
__device__ __align__(1024) __nv_bfloat16 g_hsplit[(size_t)3 * BATCH * NH * SEQ * 256];

// ---------------------------------------------------------------------------
// PTX helpers (portable sm_80+)
// ---------------------------------------------------------------------------
__device__ __forceinline__ uint32_t smem_u32(const void* p) {
    uint32_t a;
    asm("{ .reg .u64 t; cvta.to.shared.u64 t, %1; cvt.u32.u64 %0, t; }"
        : "=r"(a) : "l"(p));
    return a;
}
__device__ __forceinline__ void cp16(uint32_t s, const void* g) {
    asm volatile("cp.async.cg.shared.global [%0], [%1], 16;" :: "r"(s), "l"(g));
}
__device__ __forceinline__ void cp_commit() {
    asm volatile("cp.async.commit_group;" ::: "memory");
}
template<int N> __device__ __forceinline__ void cp_wait() {
    asm volatile("cp.async.wait_group %0;" :: "n"(N) : "memory");
}
__device__ __forceinline__ void ldsm_x4(uint32_t& r0, uint32_t& r1,
                                        uint32_t& r2, uint32_t& r3, uint32_t addr) {
    asm volatile("ldmatrix.sync.aligned.m8n8.x4.shared.b16 {%0,%1,%2,%3}, [%4];"
                 : "=r"(r0), "=r"(r1), "=r"(r2), "=r"(r3) : "r"(addr));
}
__device__ __forceinline__ void ldsm_x4_t(uint32_t& r0, uint32_t& r1,
                                          uint32_t& r2, uint32_t& r3, uint32_t addr) {
    asm volatile("ldmatrix.sync.aligned.m8n8.x4.trans.shared.b16 {%0,%1,%2,%3}, [%4];"
                 : "=r"(r0), "=r"(r1), "=r"(r2), "=r"(r3) : "r"(addr));
}
__device__ __forceinline__ void mma_bf16(float& d0, float& d1, float& d2, float& d3,
                                         uint32_t a0, uint32_t a1, uint32_t a2, uint32_t a3,
                                         uint32_t b0, uint32_t b1) {
    asm volatile(
        "mma.sync.aligned.m16n8k16.row.col.f32.bf16.bf16.f32 "
        "{%0,%1,%2,%3}, {%4,%5,%6,%7}, {%8,%9}, {%0,%1,%2,%3};"
        : "+f"(d0), "+f"(d1), "+f"(d2), "+f"(d3)
        : "r"(a0), "r"(a1), "r"(a2), "r"(a3), "r"(b0), "r"(b1));
}
__device__ __forceinline__ uint32_t pack_bf16(float a, float b) {
    __nv_bfloat162 t = __float22bfloat162_rn(make_float2(a, b));
    return *(uint32_t*)&t;
}
__device__ __forceinline__ float2 unpack_bf16(uint32_t u) {
    __nv_bfloat162 t = *(__nv_bfloat162*)&u;
    return __bfloat1622float2(t);
}
// MUFU-free exp2 (FMA/ALU pipes only). Valid for x <= ~0; err ~2e-6.
__device__ __forceinline__ float fexp2(float x) {
    x = fmaxf(x, -126.f);
    float t  = __fadd_rn(x, 12582912.f);            // round-to-nearest int in mantissa
    int   i  = __float_as_int(t) << 23;             // = r << 23 (exact)
    float xf = x - __fsub_rn(t, 12582912.f);        // frac in [-0.5, 0.5]
    float p  = 1.3333558e-3f;
    p = fmaf(p, xf, 9.6181291e-3f);
    p = fmaf(p, xf, 5.5504109e-2f);
    p = fmaf(p, xf, 2.4022651e-1f);
    p = fmaf(p, xf, 6.9314718e-1f);
    p = fmaf(p, xf, 1.0f);
    return __int_as_float(i + __float_as_int(p));
}

// ---------------------------------------------------------------------------
// Split kernel: fp32 [R,2048] -> bf16 [R,6144]; mode0 [hi|lo|hi], mode1 [hi|hi|lo]
// ---------------------------------------------------------------------------
__global__ __launch_bounds__(256)
void split_kernel(const float4* __restrict__ in, __nv_bfloat162* __restrict__ out,
                  int nvec, int mode)
{
    int i = blockIdx.x * blockDim.x + threadIdx.x;
    if (i >= nvec) return;
    float4 v = in[i];
    int r = i >> 9;
    int c = (i & 511) << 2;

    __nv_bfloat16 h0 = __float2bfloat16(v.x);
    __nv_bfloat16 h1 = __float2bfloat16(v.y);
    __nv_bfloat16 h2 = __float2bfloat16(v.z);
    __nv_bfloat16 h3 = __float2bfloat16(v.w);
    __nv_bfloat16 l0 = __float2bfloat16(v.x - __bfloat162float(h0));
    __nv_bfloat16 l1 = __float2bfloat16(v.y - __bfloat162float(h1));
    __nv_bfloat16 l2 = __float2bfloat16(v.z - __bfloat162float(h2));
    __nv_bfloat16 l3 = __float2bfloat16(v.w - __bfloat162float(h3));

    __nv_bfloat162 hA = __halves2bfloat162(h0, h1);
    __nv_bfloat162 hB = __halves2bfloat162(h2, h3);
    __nv_bfloat162 lA = __halves2bfloat162(l0, l1);
    __nv_bfloat162 lB = __halves2bfloat162(l2, l3);

    size_t base = (size_t)r * 3072 + (c >> 1);
    if (mode == 0) {
        out[base]        = hA; out[base + 1]    = hB;
        out[base + 1024] = lA; out[base + 1025] = lB;
        out[base + 2048] = hA; out[base + 2049] = hB;
    } else {
        out[base]        = hA; out[base + 1]    = hB;
        out[base + 1024] = hA; out[base + 1025] = hB;
        out[base + 2048] = lA; out[base + 2049] = lB;
    }
}

// ---------------------------------------------------------------------------
// bf16 HMMA GEMM, templated epilogue:
//   QKV_EPI=0: C = fp32 + bias (dense projection -> out)
//   QKV_EPI=1: write bf16 hi/lo per-head split into H (g_hsplit), bias added
// ---------------------------------------------------------------------------
#define CHUNKS  (KSPLIT / 32)
#define STAGES  4
#define ROWB    80
#define A_BYTES (128 * ROWB)
#define B_BYTES (256 * ROWB)
#define STAGE_B (A_BYTES + B_BYTES)
#define GEMM_SMEM (STAGES * STAGE_B)

template<int QKV_EPI>
__global__ __launch_bounds__(256, 1)
void gemm_mma_kernel(const __nv_bfloat16* __restrict__ A,
                     const __nv_bfloat16* __restrict__ B,
                     const float* __restrict__ bias,
                     float* __restrict__ C,
                     __nv_bfloat16* __restrict__ H,
                     int N)
{
    extern __shared__ __align__(128) char smem[];
    const uint32_t sb = smem_u32(smem);

    const int tid  = threadIdx.x;
    const int wid  = tid >> 5;
    const int lane = tid & 31;
    const int wm   = wid & 1;
    const int wn   = wid >> 1;
    const int m0   = blockIdx.y * 128;
    const int n0   = blockIdx.x * 256;

    const int a_row = (lane & 7) + ((lane >> 3) & 1) * 8;
    const int a_k8  = (lane >> 4) & 1;
    const int b_nrw = (lane & 7) + ((lane >> 4) & 1) * 8;
    const int b_k8  = (lane >> 3) & 1;

    const int ar[2] = { (tid + 0) >> 2, (tid + 256) >> 2 };
    const int ac    = tid & 3;

    float acc[4][8][4];
#pragma unroll
    for (int i = 0; i < 4; ++i)
#pragma unroll
        for (int j = 0; j < 8; ++j)
#pragma unroll
            for (int q = 0; q < 4; ++q) acc[i][j][q] = 0.f;

    auto load_stage = [&](int slot, int kk) {
        const uint32_t sa  = sb + slot * STAGE_B;
        const uint32_t sbb = sa + A_BYTES;
        const __nv_bfloat16* Ak = A + (size_t)m0 * KSPLIT + kk * 32;
        const __nv_bfloat16* Bk = B + (size_t)n0 * KSPLIT + kk * 32;
#pragma unroll
        for (int i = 0; i < 2; ++i) {
            int r = ar[i];
            cp16(sa + r * ROWB + ac * 16, Ak + (size_t)r * KSPLIT + ac * 8);
        }
#pragma unroll
        for (int i = 0; i < 4; ++i) {
            int idx = tid + i * 256;
            int r = idx >> 2, c = idx & 3;
            cp16(sbb + r * ROWB + c * 16, Bk + (size_t)r * KSPLIT + c * 8);
        }
    };

#pragma unroll
    for (int s = 0; s < STAGES - 1; ++s) { load_stage(s, s); cp_commit(); }

    for (int k = 0; k < CHUNKS; ++k) {
        const int s = k & (STAGES - 1);
        cp_wait<STAGES - 2>();
        __syncthreads();

        if (k + STAGES - 1 < CHUNKS) load_stage((k + STAGES - 1) & (STAGES - 1),
                                                 k + STAGES - 1);
        cp_commit();

        const uint32_t sa  = sb + s * STAGE_B + (wm * 64) * ROWB;
        const uint32_t sbb = sb + s * STAGE_B + A_BYTES + (wn * 64) * ROWB;

#pragma unroll
        for (int kk = 0; kk < 2; ++kk) {
            uint32_t a[4][4];
            uint32_t bfr[8][2];
#pragma unroll
            for (int mt = 0; mt < 4; ++mt) {
                uint32_t addr = sa + (mt * 16 + a_row) * ROWB + (kk * 2 + a_k8) * 16;
                ldsm_x4(a[mt][0], a[mt][1], a[mt][2], a[mt][3], addr);
            }
#pragma unroll
            for (int np = 0; np < 4; ++np) {
                uint32_t addr = sbb + (np * 16 + b_nrw) * ROWB + (kk * 2 + b_k8) * 16;
                uint32_t r0, r1, r2, r3;
                ldsm_x4(r0, r1, r2, r3, addr);
                bfr[np * 2 + 0][0] = r0; bfr[np * 2 + 0][1] = r1;
                bfr[np * 2 + 1][0] = r2; bfr[np * 2 + 1][1] = r3;
            }
#pragma unroll
            for (int mt = 0; mt < 4; ++mt)
#pragma unroll
                for (int nt = 0; nt < 8; ++nt)
                    mma_bf16(acc[mt][nt][0], acc[mt][nt][1],
                             acc[mt][nt][2], acc[mt][nt][3],
                             a[mt][0], a[mt][1], a[mt][2], a[mt][3],
                             bfr[nt][0], bfr[nt][1]);
        }
    }

    const int g  = lane >> 2;
    const int ti = lane & 3;

    if (QKV_EPI == 0) {
#pragma unroll
        for (int mt = 0; mt < 4; ++mt) {
            const int row = m0 + wm * 64 + mt * 16 + g;
#pragma unroll
            for (int nt = 0; nt < 8; ++nt) {
                const int col = n0 + wn * 64 + nt * 8 + ti * 2;
                float2 bv = *(const float2*)(bias + col);
                float2 o0 = make_float2(acc[mt][nt][0] + bv.x, acc[mt][nt][1] + bv.y);
                float2 o1 = make_float2(acc[mt][nt][2] + bv.x, acc[mt][nt][3] + bv.y);
                *(float2*)(C + (size_t)row * N + col)       = o0;
                *(float2*)(C + (size_t)(row + 8) * N + col) = o1;
            }
        }
    } else {
        // fused hi/lo per-head split: H[sel][b][h][s][hi128|lo128]
#pragma unroll
        for (int mt = 0; mt < 4; ++mt) {
            const int row = m0 + wm * 64 + mt * 16 + g;
            const int b   = row >> 11;
            const int sidx = row & 2047;
#pragma unroll
            for (int nt = 0; nt < 8; ++nt) {
                const int col = n0 + wn * 64 + nt * 8 + ti * 2;
                const int sel = col >> 11;
                const int hh  = (col >> 7) & 15;
                const int d   = col & 127;
                float2 bv = *(const float2*)(bias + col);
                size_t base = ((((size_t)sel * BATCH + b) * NH + hh) * SEQ + sidx) * 256 + d;
#pragma unroll
                for (int half = 0; half < 2; ++half) {
                    float v0 = acc[mt][nt][half * 2 + 0] + bv.x;
                    float v1 = acc[mt][nt][half * 2 + 1] + bv.y;
                    __nv_bfloat16 h0 = __float2bfloat16(v0);
                    __nv_bfloat16 h1 = __float2bfloat16(v1);
                    __nv_bfloat16 l0 = __float2bfloat16(v0 - __bfloat162float(h0));
                    __nv_bfloat16 l1 = __float2bfloat16(v1 - __bfloat162float(h1));
                    size_t bb = base + (size_t)half * 8 * 256;
                    *(__nv_bfloat162*)(H + bb)       = __halves2bfloat162(h0, h1);
                    *(__nv_bfloat162*)(H + bb + 128) = __halves2bfloat162(l0, l1);
                }
            }
        }
    }
}

// ---------------------------------------------------------------------------
// Flash attention, bf16 HMMA, split precision, causal, MUFU-free softmax.
// Bq=128 (8 warps x 16 rows), Bk=64, D=128. Epilogue writes g_ab [hi|lo|hi].
// ---------------------------------------------------------------------------
#define FROWB 272
#define FTILE (64 * FROWB)
#define FSTAGE (4 * FTILE)
#define FLASH_SMEM (2 * FSTAGE)

__global__ __launch_bounds__(256, 1)
void flash_mma_kernel(const __nv_bfloat16* __restrict__ gs,
                      __nv_bfloat16* __restrict__ Aout)
{
    extern __shared__ __align__(128) char smem[];
    const uint32_t sb = smem_u32(smem);

    const int bid = blockIdx.x;
    const int qt  = 15 - (bid >> 6);
    const int sub = bid & 63;
    const int h   = sub & 15;
    const int b   = sub >> 4;
    const int q0  = qt * 128;
    const int nkt = 2 * qt + 2;

    const int tid  = threadIdx.x;
    const int w    = tid >> 5;
    const int lane = tid & 31;
    const int g    = lane >> 2;
    const int ti   = lane & 3;
    // softmax scale folded with log2(e): probs computed via exp2
    const float scl2 = 0.08838834764831845f * 1.4426950408889634f;

    const __nv_bfloat16* gq = gs + (((size_t)0 * BATCH + b) * NH + h) * SEQ * 256;
    const __nv_bfloat16* gk = gs + (((size_t)1 * BATCH + b) * NH + h) * SEQ * 256;
    const __nv_bfloat16* gv = gs + (((size_t)2 * BATCH + b) * NH + h) * SEQ * 256;

    // ---- load Q (hi+lo) into stage0 smem ----
    {
#pragma unroll
        for (int i = 0; i < 16; ++i) {
            int idx = tid + i * 256;
            int r = idx >> 5;
            int rem = idx & 31;
            int part = rem >> 4;
            int c = rem & 15;
            cp16(sb + part * (128 * FROWB) + r * FROWB + c * 16,
                 gq + ((size_t)(q0 + r)) * 256 + part * 128 + c * 8);
        }
        cp_commit();
        cp_wait<0>();
        __syncthreads();
    }

    uint32_t qh[8][4], qlr[8][4];
    {
        int r  = w * 16 + (lane & 15);
        int cb = ((lane >> 4) & 1) * 16;
#pragma unroll
        for (int c = 0; c < 8; ++c) {
            ldsm_x4(qh[c][0], qh[c][1], qh[c][2], qh[c][3],
                    sb + r * FROWB + c * 32 + cb);
            ldsm_x4(qlr[c][0], qlr[c][1], qlr[c][2], qlr[c][3],
                    sb + 128 * FROWB + r * FROWB + c * 32 + cb);
        }
    }
    __syncthreads();

    auto load_kv = [&](int slot, int kt) {
        const uint32_t st = sb + slot * FSTAGE;
        const int k0 = kt * 64;
#pragma unroll
        for (int i = 0; i < 16; ++i) {
            int idx = tid + i * 256;
            int tile = idx >> 10;
            int rem = idx & 1023;
            int r = rem >> 4;
            int c = rem & 15;
            const __nv_bfloat16* src;
            if (tile == 0)      src = gk + ((size_t)(k0 + r)) * 256 +       c * 8;
            else if (tile == 1) src = gk + ((size_t)(k0 + r)) * 256 + 128 + c * 8;
            else if (tile == 2) src = gv + ((size_t)(k0 + r)) * 256 +       c * 8;
            else                src = gv + ((size_t)(k0 + r)) * 256 + 128 + c * 8;
            cp16(st + tile * FTILE + r * FROWB + c * 16, src);
        }
    };

    load_kv(0, 0); cp_commit();
    load_kv(1, 1); cp_commit();

    float m_g = -1e30f, m_g8 = -1e30f, l_g = 0.f, l_g8 = 0.f;
    float o[16][4];
#pragma unroll
    for (int t = 0; t < 16; ++t)
#pragma unroll
        for (int q = 0; q < 4; ++q) o[t][q] = 0.f;

    const int b_row = (lane & 7) + ((lane >> 4) & 1) * 8;
    const int b_k   = ((lane >> 3) & 1) * 16;
    const int v_row = (lane & 7) + ((lane >> 3) & 1) * 8;
    const int v_cb  = ((lane >> 4) & 1) * 16;
    const int row_g = q0 + w * 16 + g;

    for (int kt = 0; kt < nkt; ++kt) {
        const int s = kt & 1;
        const int k0 = kt * 64;
        cp_wait<1>();
        __syncthreads();

        if (k0 <= q0 + w * 16 + 15) {
            const uint32_t sKh = sb + s * FSTAGE;
            const uint32_t sKl = sKh + FTILE;
            const uint32_t sVh = sKh + 2 * FTILE;
            const uint32_t sVl = sKh + 3 * FTILE;

            float s4[8][4];
#pragma unroll
            for (int j = 0; j < 8; ++j)
#pragma unroll
                for (int q = 0; q < 4; ++q) s4[j][q] = 0.f;

#pragma unroll
            for (int c8 = 0; c8 < 8; ++c8) {
                uint32_t bb[8][2];
#pragma unroll
                for (int np = 0; np < 4; ++np) {
                    uint32_t r0, r1, r2, r3;
                    ldsm_x4(r0, r1, r2, r3,
                            sKh + (np * 16 + b_row) * FROWB + c8 * 32 + b_k);
                    bb[2*np][0] = r0; bb[2*np][1] = r1;
                    bb[2*np+1][0] = r2; bb[2*np+1][1] = r3;
                }
#pragma unroll
                for (int j = 0; j < 8; ++j)
                    mma_bf16(s4[j][0], s4[j][1], s4[j][2], s4[j][3],
                             qh[c8][0], qh[c8][1], qh[c8][2], qh[c8][3],
                             bb[j][0], bb[j][1]);
#pragma unroll
                for (int j = 0; j < 8; ++j)
                    mma_bf16(s4[j][0], s4[j][1], s4[j][2], s4[j][3],
                             qlr[c8][0], qlr[c8][1], qlr[c8][2], qlr[c8][3],
                             bb[j][0], bb[j][1]);
#pragma unroll
                for (int np = 0; np < 4; ++np) {
                    uint32_t r0, r1, r2, r3;
                    ldsm_x4(r0, r1, r2, r3,
                            sKl + (np * 16 + b_row) * FROWB + c8 * 32 + b_k);
                    bb[2*np][0] = r0; bb[2*np][1] = r1;
                    bb[2*np+1][0] = r2; bb[2*np+1][1] = r3;
                }
#pragma unroll
                for (int j = 0; j < 8; ++j)
                    mma_bf16(s4[j][0], s4[j][1], s4[j][2], s4[j][3],
                             qh[c8][0], qh[c8][1], qh[c8][2], qh[c8][3],
                             bb[j][0], bb[j][1]);
            }

            const bool diag = (k0 + 63 > q0 + w * 16);
#pragma unroll
            for (int j = 0; j < 8; ++j) {
                int col = k0 + j * 8 + 2 * ti;
                s4[j][0] *= scl2; s4[j][1] *= scl2;
                s4[j][2] *= scl2; s4[j][3] *= scl2;
                if (diag) {
                    if (col     > row_g)     s4[j][0] = -1e30f;
                    if (col + 1 > row_g)     s4[j][1] = -1e30f;
                    if (col     > row_g + 8) s4[j][2] = -1e30f;
                    if (col + 1 > row_g + 8) s4[j][3] = -1e30f;
                }
            }

            float tm_g = -1e30f, tm_g8 = -1e30f;
#pragma unroll
            for (int j = 0; j < 8; ++j) {
                tm_g  = fmaxf(tm_g,  fmaxf(s4[j][0], s4[j][1]));
                tm_g8 = fmaxf(tm_g8, fmaxf(s4[j][2], s4[j][3]));
            }
            tm_g  = fmaxf(tm_g,  __shfl_xor_sync(0xffffffffu, tm_g, 1));
            tm_g  = fmaxf(tm_g,  __shfl_xor_sync(0xffffffffu, tm_g, 2));
            tm_g8 = fmaxf(tm_g8, __shfl_xor_sync(0xffffffffu, tm_g8, 1));
            tm_g8 = fmaxf(tm_g8, __shfl_xor_sync(0xffffffffu, tm_g8, 2));

            float mn_g  = fmaxf(m_g,  tm_g);
            float mn_g8 = fmaxf(m_g8, tm_g8);
            float corr_g  = fexp2(m_g  - mn_g);
            float corr_g8 = fexp2(m_g8 - mn_g8);

            float sum_g = 0.f, sum_g8 = 0.f;
#pragma unroll
            for (int j = 0; j < 8; ++j) {
                s4[j][0] = fexp2(s4[j][0] - mn_g);
                s4[j][1] = fexp2(s4[j][1] - mn_g);
                s4[j][2] = fexp2(s4[j][2] - mn_g8);
                s4[j][3] = fexp2(s4[j][3] - mn_g8);
                sum_g  += s4[j][0] + s4[j][1];
                sum_g8 += s4[j][2] + s4[j][3];
            }
            sum_g  += __shfl_xor_sync(0xffffffffu, sum_g, 1);
            sum_g  += __shfl_xor_sync(0xffffffffu, sum_g, 2);
            sum_g8 += __shfl_xor_sync(0xffffffffu, sum_g8, 1);
            sum_g8 += __shfl_xor_sync(0xffffffffu, sum_g8, 2);

            l_g  = l_g  * corr_g  + sum_g;   m_g  = mn_g;
            l_g8 = l_g8 * corr_g8 + sum_g8;  m_g8 = mn_g8;

#pragma unroll
            for (int t = 0; t < 16; ++t) {
                o[t][0] *= corr_g;  o[t][1] *= corr_g;
                o[t][2] *= corr_g8; o[t][3] *= corr_g8;
            }

#pragma unroll
            for (int c = 0; c < 4; ++c) {
                uint32_t aPh[4], aPl[4];
                aPh[0] = pack_bf16(s4[2*c][0],   s4[2*c][1]);
                aPh[1] = pack_bf16(s4[2*c][2],   s4[2*c][3]);
                aPh[2] = pack_bf16(s4[2*c+1][0], s4[2*c+1][1]);
                aPh[3] = pack_bf16(s4[2*c+1][2], s4[2*c+1][3]);
                {
                    float2 u;
                    u = unpack_bf16(aPh[0]);
                    aPl[0] = pack_bf16(s4[2*c][0] - u.x,   s4[2*c][1] - u.y);
                    u = unpack_bf16(aPh[1]);
                    aPl[1] = pack_bf16(s4[2*c][2] - u.x,   s4[2*c][3] - u.y);
                    u = unpack_bf16(aPh[2]);
                    aPl[2] = pack_bf16(s4[2*c+1][0] - u.x, s4[2*c+1][1] - u.y);
                    u = unpack_bf16(aPh[3]);
                    aPl[3] = pack_bf16(s4[2*c+1][2] - u.x, s4[2*c+1][3] - u.y);
                }
#pragma unroll
                for (int dh = 0; dh < 2; ++dh) {
                    uint32_t bv[8][2];
#pragma unroll
                    for (int dd = 0; dd < 4; ++dd) {
                        uint32_t r0, r1, r2, r3;
                        ldsm_x4_t(r0, r1, r2, r3,
                                  sVh + (c * 16 + v_row) * FROWB
                                      + (dh * 4 + dd) * 32 + v_cb);
                        bv[2*dd][0] = r0; bv[2*dd][1] = r1;
                        bv[2*dd+1][0] = r2; bv[2*dd+1][1] = r3;
                    }
#pragma unroll
                    for (int tt = 0; tt < 8; ++tt) {
                        int t = dh * 8 + tt;
                        mma_bf16(o[t][0], o[t][1], o[t][2], o[t][3],
                                 aPh[0], aPh[1], aPh[2], aPh[3],
                                 bv[tt][0], bv[tt][1]);
                        mma_bf16(o[t][0], o[t][1], o[t][2], o[t][3],
                                 aPl[0], aPl[1], aPl[2], aPl[3],
                                 bv[tt][0], bv[tt][1]);
                    }
#pragma unroll
                    for (int dd = 0; dd < 4; ++dd) {
                        uint32_t r0, r1, r2, r3;
                        ldsm_x4_t(r0, r1, r2, r3,
                                  sVl + (c * 16 + v_row) * FROWB
                                      + (dh * 4 + dd) * 32 + v_cb);
                        bv[2*dd][0] = r0; bv[2*dd][1] = r1;
                        bv[2*dd+1][0] = r2; bv[2*dd+1][1] = r3;
                    }
#pragma unroll
                    for (int tt = 0; tt < 8; ++tt) {
                        int t = dh * 8 + tt;
                        mma_bf16(o[t][0], o[t][1], o[t][2], o[t][3],
                                 aPh[0], aPh[1], aPh[2], aPh[3],
                                 bv[tt][0], bv[tt][1]);
                    }
                }
            }
        }

        __syncthreads();
        if (kt + 2 < nkt) { load_kv(s, kt + 2); cp_commit(); }
    }

    // ---- fused epilogue: normalize + hi/lo split into g_ab [hi|lo|hi] ----
    const float inv_g  = 1.f / l_g;
    const float inv_g8 = 1.f / l_g8;
    const size_t row_i = (size_t)(b * SEQ + q0 + w * 16 + g);
    __nv_bfloat16* a0 = Aout + row_i * KSPLIT + h * HD;
    __nv_bfloat16* a8 = a0 + (size_t)8 * KSPLIT;
#pragma unroll
    for (int t = 0; t < 16; ++t) {
        int d = t * 8 + 2 * ti;
        {
            float v0 = o[t][0] * inv_g, v1 = o[t][1] * inv_g;
            __nv_bfloat16 h0 = __float2bfloat16(v0);
            __nv_bfloat16 h1 = __float2bfloat16(v1);
            __nv_bfloat16 l0 = __float2bfloat16(v0 - __bfloat162float(h0));
            __nv_bfloat16 l1 = __float2bfloat16(v1 - __bfloat162float(h1));
            __nv_bfloat162 hp = __halves2bfloat162(h0, h1);
            *(__nv_bfloat162*)(a0 + d)        = hp;
            *(__nv_bfloat162*)(a0 + 2048 + d) = __halves2bfloat162(l0, l1);
            *(__nv_bfloat162*)(a0 + 4096 + d) = hp;
        }
        {
            float v0 = o[t][2] * inv_g8, v1 = o[t][3] * inv_g8;
            __nv_bfloat16 h0 = __float2bfloat16(v0);
            __nv_bfloat16 h1 = __float2bfloat16(v1);
            __nv_bfloat16 l0 = __float2bfloat16(v0 - __bfloat162float(h0));
            __nv_bfloat16 l1 = __float2bfloat16(v1 - __bfloat162float(h1));
            __nv_bfloat162 hp = __halves2bfloat162(h0, h1);
            *(__nv_bfloat162*)(a8 + d)        = hp;
            *(__nv_bfloat162*)(a8 + 2048 + d) = __halves2bfloat162(l0, l1);
            *(__nv_bfloat162*)(a8 + 4096 + d) = hp;
        }
    }
}

// ---------------------------------------------------------------------------
// Host side
// ---------------------------------------------------------------------------
extern "C" void kernel_launch(void* const* d_in, const int* in_sizes, int n_in,
                              void* d_out, int out_size)
{
    (void)in_sizes; (void)n_in; (void)out_size;
    const float* hs      = (const float*)d_in[0];
    const float* w_qkv   = (const float*)d_in[1];
    const float* b_qkv   = (const float*)d_in[2];
    const float* w_dense = (const float*)d_in[3];
    const float* b_dense = (const float*)d_in[4];
    float* out = (float*)d_out;

    void *p_ab, *p_bqkv, *p_bdense, *p_hs;
    cudaGetSymbolAddress(&p_ab, g_ab);
    cudaGetSymbolAddress(&p_bqkv, g_bqkv);
    cudaGetSymbolAddress(&p_bdense, g_bdense);
    cudaGetSymbolAddress(&p_hs, g_hsplit);

    static bool attr_done = false;
    if (!attr_done) {
        cudaFuncSetAttribute(gemm_mma_kernel<0>,
                             cudaFuncAttributeMaxDynamicSharedMemorySize, GEMM_SMEM);
        cudaFuncSetAttribute(gemm_mma_kernel<1>,
                             cudaFuncAttributeMaxDynamicSharedMemorySize, GEMM_SMEM);
        cudaFuncSetAttribute(flash_mma_kernel,
                             cudaFuncAttributeMaxDynamicSharedMemorySize, FLASH_SMEM);
        attr_done = true;
    }

    // 1) split inputs to bf16 hi/lo
    {
        int nv = MROWS * HID / 4;
        split_kernel<<<(nv + 255) / 256, 256>>>((const float4*)hs,
                                                (__nv_bfloat162*)p_ab, nv, 0);
        nv = QKVN * HID / 4;
        split_kernel<<<(nv + 255) / 256, 256>>>((const float4*)w_qkv,
                                                (__nv_bfloat162*)p_bqkv, nv, 1);
        nv = HID * HID / 4;
        split_kernel<<<(nv + 255) / 256, 256>>>((const float4*)w_dense,
                                                (__nv_bfloat162*)p_bdense, nv, 1);
    }

    // 2) QKV projection, fused per-head hi/lo split epilogue
    {
        dim3 g(QKVN / 256, MROWS / 128);
        gemm_mma_kernel<1><<<g, 256, GEMM_SMEM>>>(
            (const __nv_bfloat16*)p_ab, (const __nv_bfloat16*)p_bqkv,
            b_qkv, nullptr, (__nv_bfloat16*)p_hs, QKVN);
    }

    // 3) flash attention (HMMA), fused split epilogue into g_ab
    {
        flash_mma_kernel<<<1024, 256, FLASH_SMEM>>>(
            (const __nv_bfloat16*)p_hs, (__nv_bfloat16*)p_ab);
    }

    // 4) dense projection
    {
        dim3 g(HID / 256, MROWS / 128);
        gemm_mma_kernel<0><<<g, 256, GEMM_SMEM>>>(
            (const __nv_bfloat16*)p_ab, (const __nv_bfloat16*)p_bdense,
            b_dense, out, nullptr, HID);
    }
}

// round 6
// speedup vs baseline: 1.1512x; 1.1512x over previous
#include <cuda_runtime.h>
#include <cuda_bf16.h>
#include <math.h>
#include <stdint.h>

#define HID   2048
#define NH    16
#define HD    128
#define BATCH 4
#define SEQ   2048
#define MROWS (BATCH*SEQ)     // 8192
#define QKVN  (3*HID)         // 6144
#define KSPLIT (3*HID)        // 6144

// ---------------------------------------------------------------------------
// Scratch
// ---------------------------------------------------------------------------
__device__ __align__(1024) __nv_bfloat16 g_ab[(size_t)MROWS * KSPLIT];
__device__ __align__(1024) __nv_bfloat16 g_bqkv[(size_t)QKVN * KSPLIT];
__device__ __align__(1024) __nv_bfloat16 g_bdense[(size_t)HID * KSPLIT];
// per-head split layout: [sel(q,k,v)][b][h][s][hi128|lo128]
__device__ __align__(1024) __nv_bfloat16 g_hsplit[(size_t)3 * BATCH * NH * SEQ * 256];

// ---------------------------------------------------------------------------
// PTX helpers (portable sm_80+)
// ---------------------------------------------------------------------------
__device__ __forceinline__ uint32_t smem_u32(const void* p) {
    uint32_t a;
    asm("{ .reg .u64 t; cvta.to.shared.u64 t, %1; cvt.u32.u64 %0, t; }"
        : "=r"(a) : "l"(p));
    return a;
}
__device__ __forceinline__ void cp16(uint32_t s, const void* g) {
    asm volatile("cp.async.cg.shared.global [%0], [%1], 16;" :: "r"(s), "l"(g));
}
__device__ __forceinline__ void cp_commit() {
    asm volatile("cp.async.commit_group;" ::: "memory");
}
template<int N> __device__ __forceinline__ void cp_wait() {
    asm volatile("cp.async.wait_group %0;" :: "n"(N) : "memory");
}
__device__ __forceinline__ void ldsm_x4(uint32_t& r0, uint32_t& r1,
                                        uint32_t& r2, uint32_t& r3, uint32_t addr) {
    asm volatile("ldmatrix.sync.aligned.m8n8.x4.shared.b16 {%0,%1,%2,%3}, [%4];"
                 : "=r"(r0), "=r"(r1), "=r"(r2), "=r"(r3) : "r"(addr));
}
__device__ __forceinline__ void ldsm_x4_t(uint32_t& r0, uint32_t& r1,
                                          uint32_t& r2, uint32_t& r3, uint32_t addr) {
    asm volatile("ldmatrix.sync.aligned.m8n8.x4.trans.shared.b16 {%0,%1,%2,%3}, [%4];"
                 : "=r"(r0), "=r"(r1), "=r"(r2), "=r"(r3) : "r"(addr));
}
__device__ __forceinline__ void mma_bf16(float& d0, float& d1, float& d2, float& d3,
                                         uint32_t a0, uint32_t a1, uint32_t a2, uint32_t a3,
                                         uint32_t b0, uint32_t b1) {
    asm volatile(
        "mma.sync.aligned.m16n8k16.row.col.f32.bf16.bf16.f32 "
        "{%0,%1,%2,%3}, {%4,%5,%6,%7}, {%8,%9}, {%0,%1,%2,%3};"
        : "+f"(d0), "+f"(d1), "+f"(d2), "+f"(d3)
        : "r"(a0), "r"(a1), "r"(a2), "r"(a3), "r"(b0), "r"(b1));
}
__device__ __forceinline__ uint32_t pack_bf16(float a, float b) {
    __nv_bfloat162 t = __float22bfloat162_rn(make_float2(a, b));
    return *(uint32_t*)&t;
}
__device__ __forceinline__ float2 unpack_bf16(uint32_t u) {
    __nv_bfloat162 t = *(__nv_bfloat162*)&u;
    return __bfloat1622float2(t);
}
// MUFU-free exp2 (FMA/ALU pipes only). Valid for x <= ~0; err ~2e-6.
__device__ __forceinline__ float fexp2(float x) {
    x = fmaxf(x, -126.f);
    float t  = __fadd_rn(x, 12582912.f);
    int   i  = __float_as_int(t) << 23;
    float xf = x - __fsub_rn(t, 12582912.f);
    float p  = 1.3333558e-3f;
    p = fmaf(p, xf, 9.6181291e-3f);
    p = fmaf(p, xf, 5.5504109e-2f);
    p = fmaf(p, xf, 2.4022651e-1f);
    p = fmaf(p, xf, 6.9314718e-1f);
    p = fmaf(p, xf, 1.0f);
    return __int_as_float(i + __float_as_int(p));
}

// ---------------------------------------------------------------------------
// Split kernel: fp32 [R,2048] -> bf16 [R,6144]; mode0 [hi|lo|hi], mode1 [hi|hi|lo]
// ---------------------------------------------------------------------------
__global__ __launch_bounds__(256)
void split_kernel(const float4* __restrict__ in, __nv_bfloat162* __restrict__ out,
                  int nvec, int mode)
{
    int i = blockIdx.x * blockDim.x + threadIdx.x;
    if (i >= nvec) return;
    float4 v = in[i];
    int r = i >> 9;
    int c = (i & 511) << 2;

    __nv_bfloat16 h0 = __float2bfloat16(v.x);
    __nv_bfloat16 h1 = __float2bfloat16(v.y);
    __nv_bfloat16 h2 = __float2bfloat16(v.z);
    __nv_bfloat16 h3 = __float2bfloat16(v.w);
    __nv_bfloat16 l0 = __float2bfloat16(v.x - __bfloat162float(h0));
    __nv_bfloat16 l1 = __float2bfloat16(v.y - __bfloat162float(h1));
    __nv_bfloat16 l2 = __float2bfloat16(v.z - __bfloat162float(h2));
    __nv_bfloat16 l3 = __float2bfloat16(v.w - __bfloat162float(h3));

    __nv_bfloat162 hA = __halves2bfloat162(h0, h1);
    __nv_bfloat162 hB = __halves2bfloat162(h2, h3);
    __nv_bfloat162 lA = __halves2bfloat162(l0, l1);
    __nv_bfloat162 lB = __halves2bfloat162(l2, l3);

    size_t base = (size_t)r * 3072 + (c >> 1);
    if (mode == 0) {
        out[base]        = hA; out[base + 1]    = hB;
        out[base + 1024] = lA; out[base + 1025] = lB;
        out[base + 2048] = hA; out[base + 2049] = hB;
    } else {
        out[base]        = hA; out[base + 1]    = hB;
        out[base + 1024] = hA; out[base + 1025] = hB;
        out[base + 2048] = lA; out[base + 2049] = lB;
    }
}

// ---------------------------------------------------------------------------
// bf16 HMMA GEMM, K-chunk 64, 3 stages, fragment double buffering.
//   QKV_EPI=0: C = fp32 + bias
//   QKV_EPI=1: bf16 hi/lo per-head split into H, bias added
// CTA 128x256, 8 warps, warp tile 64x64.
// ---------------------------------------------------------------------------
#define NCHUNK  (KSPLIT / 64)      // 96
#define GSTAGES 3
#define ROWB    144                // 64 bf16 data (128B) + 16B pad
#define A_BYTES (128 * ROWB)       // 18432
#define B_BYTES (256 * ROWB)       // 36864
#define STAGE_B (A_BYTES + B_BYTES)
#define GEMM_SMEM (GSTAGES * STAGE_B)   // 165888

template<int QKV_EPI>
__global__ __launch_bounds__(256, 1)
void gemm_mma_kernel(const __nv_bfloat16* __restrict__ A,
                     const __nv_bfloat16* __restrict__ B,
                     const float* __restrict__ bias,
                     float* __restrict__ C,
                     __nv_bfloat16* __restrict__ H,
                     int N)
{
    extern __shared__ __align__(128) char smem[];
    const uint32_t sb = smem_u32(smem);

    const int tid  = threadIdx.x;
    const int wid  = tid >> 5;
    const int lane = tid & 31;
    const int wm   = wid & 1;
    const int wn   = wid >> 1;
    const int m0   = blockIdx.y * 128;
    const int n0   = blockIdx.x * 256;

    const int a_row = (lane & 7) + ((lane >> 3) & 1) * 8;
    const int a_k8  = (lane >> 4) & 1;
    const int b_nrw = (lane & 7) + ((lane >> 4) & 1) * 8;
    const int b_k8  = (lane >> 3) & 1;

    float acc[4][8][4];
#pragma unroll
    for (int i = 0; i < 4; ++i)
#pragma unroll
        for (int j = 0; j < 8; ++j)
#pragma unroll
            for (int q = 0; q < 4; ++q) acc[i][j][q] = 0.f;

    // per-stage loads: A 4 cp16/thread, B 8 cp16/thread
    auto load_stage = [&](int slot, int kk) {
        const uint32_t sa  = sb + slot * STAGE_B;
        const uint32_t sbb = sa + A_BYTES;
        const __nv_bfloat16* Ak = A + (size_t)m0 * KSPLIT + kk * 64;
        const __nv_bfloat16* Bk = B + (size_t)n0 * KSPLIT + kk * 64;
#pragma unroll
        for (int i = 0; i < 4; ++i) {
            int idx = tid + i * 256;
            int r = idx >> 3, c = idx & 7;
            cp16(sa + r * ROWB + c * 16, Ak + (size_t)r * KSPLIT + c * 8);
        }
#pragma unroll
        for (int i = 0; i < 8; ++i) {
            int idx = tid + i * 256;
            int r = idx >> 3, c = idx & 7;
            cp16(sbb + r * ROWB + c * 16, Bk + (size_t)r * KSPLIT + c * 8);
        }
    };

    load_stage(0, 0); cp_commit();
    load_stage(1, 1); cp_commit();

    uint32_t af[2][4][4];
    uint32_t bfr[2][8][2];

    for (int k = 0; k < NCHUNK; ++k) {
        const int s = k % GSTAGES;
        cp_wait<1>();
        __syncthreads();

        if (k + 2 < NCHUNK) load_stage((k + 2) % GSTAGES, k + 2);
        cp_commit();

        const uint32_t sa  = sb + s * STAGE_B + (wm * 64) * ROWB;
        const uint32_t sbb = sb + s * STAGE_B + A_BYTES + (wn * 64) * ROWB;

        // fragment loader for a k16 step kkv (0..3)
        auto load_frag = [&](int buf, int kkv) {
#pragma unroll
            for (int mt = 0; mt < 4; ++mt)
                ldsm_x4(af[buf][mt][0], af[buf][mt][1],
                        af[buf][mt][2], af[buf][mt][3],
                        sa + (mt * 16 + a_row) * ROWB + kkv * 32 + a_k8 * 16);
#pragma unroll
            for (int np = 0; np < 4; ++np) {
                uint32_t r0, r1, r2, r3;
                ldsm_x4(r0, r1, r2, r3,
                        sbb + (np * 16 + b_nrw) * ROWB + kkv * 32 + b_k8 * 16);
                bfr[buf][2*np][0] = r0;   bfr[buf][2*np][1] = r1;
                bfr[buf][2*np+1][0] = r2; bfr[buf][2*np+1][1] = r3;
            }
        };

        load_frag(0, 0);
#pragma unroll
        for (int kkv = 0; kkv < 4; ++kkv) {
            const int cur = kkv & 1;
            if (kkv < 3) load_frag(cur ^ 1, kkv + 1);
#pragma unroll
            for (int mt = 0; mt < 4; ++mt)
#pragma unroll
                for (int nt = 0; nt < 8; ++nt)
                    mma_bf16(acc[mt][nt][0], acc[mt][nt][1],
                             acc[mt][nt][2], acc[mt][nt][3],
                             af[cur][mt][0], af[cur][mt][1],
                             af[cur][mt][2], af[cur][mt][3],
                             bfr[cur][nt][0], bfr[cur][nt][1]);
        }
    }

    const int g  = lane >> 2;
    const int ti = lane & 3;

    if (QKV_EPI == 0) {
#pragma unroll
        for (int mt = 0; mt < 4; ++mt) {
            const int row = m0 + wm * 64 + mt * 16 + g;
#pragma unroll
            for (int nt = 0; nt < 8; ++nt) {
                const int col = n0 + wn * 64 + nt * 8 + ti * 2;
                float2 bv = *(const float2*)(bias + col);
                float2 o0 = make_float2(acc[mt][nt][0] + bv.x, acc[mt][nt][1] + bv.y);
                float2 o1 = make_float2(acc[mt][nt][2] + bv.x, acc[mt][nt][3] + bv.y);
                *(float2*)(C + (size_t)row * N + col)       = o0;
                *(float2*)(C + (size_t)(row + 8) * N + col) = o1;
            }
        }
    } else {
#pragma unroll
        for (int mt = 0; mt < 4; ++mt) {
            const int row = m0 + wm * 64 + mt * 16 + g;
            const int b   = row >> 11;
            const int sidx = row & 2047;
#pragma unroll
            for (int nt = 0; nt < 8; ++nt) {
                const int col = n0 + wn * 64 + nt * 8 + ti * 2;
                const int sel = col >> 11;
                const int hh  = (col >> 7) & 15;
                const int d   = col & 127;
                float2 bv = *(const float2*)(bias + col);
                size_t base = ((((size_t)sel * BATCH + b) * NH + hh) * SEQ + sidx) * 256 + d;
#pragma unroll
                for (int half = 0; half < 2; ++half) {
                    float v0 = acc[mt][nt][half * 2 + 0] + bv.x;
                    float v1 = acc[mt][nt][half * 2 + 1] + bv.y;
                    __nv_bfloat16 h0 = __float2bfloat16(v0);
                    __nv_bfloat16 h1 = __float2bfloat16(v1);
                    __nv_bfloat16 l0 = __float2bfloat16(v0 - __bfloat162float(h0));
                    __nv_bfloat16 l1 = __float2bfloat16(v1 - __bfloat162float(h1));
                    size_t bb = base + (size_t)half * 8 * 256;
                    *(__nv_bfloat162*)(H + bb)       = __halves2bfloat162(h0, h1);
                    *(__nv_bfloat162*)(H + bb + 128) = __halves2bfloat162(l0, l1);
                }
            }
        }
    }
}

// ---------------------------------------------------------------------------
// Flash attention, bf16 HMMA, split precision, causal, MUFU-free softmax.
// Bq=128 (8 warps x 16 rows), Bk=64, D=128. Epilogue writes g_ab [hi|lo|hi].
// ---------------------------------------------------------------------------
#define FROWB 272
#define FTILE (64 * FROWB)
#define FSTAGE (4 * FTILE)
#define FLASH_SMEM (2 * FSTAGE)

__global__ __launch_bounds__(256, 1)
void flash_mma_kernel(const __nv_bfloat16* __restrict__ gs,
                      __nv_bfloat16* __restrict__ Aout)
{
    extern __shared__ __align__(128) char smem[];
    const uint32_t sb = smem_u32(smem);

    const int bid = blockIdx.x;
    const int qt  = 15 - (bid >> 6);
    const int sub = bid & 63;
    const int h   = sub & 15;
    const int b   = sub >> 4;
    const int q0  = qt * 128;
    const int nkt = 2 * qt + 2;

    const int tid  = threadIdx.x;
    const int w    = tid >> 5;
    const int lane = tid & 31;
    const int g    = lane >> 2;
    const int ti   = lane & 3;
    const float scl2 = 0.08838834764831845f * 1.4426950408889634f;

    const __nv_bfloat16* gq = gs + (((size_t)0 * BATCH + b) * NH + h) * SEQ * 256;
    const __nv_bfloat16* gk = gs + (((size_t)1 * BATCH + b) * NH + h) * SEQ * 256;
    const __nv_bfloat16* gv = gs + (((size_t)2 * BATCH + b) * NH + h) * SEQ * 256;

    {
#pragma unroll
        for (int i = 0; i < 16; ++i) {
            int idx = tid + i * 256;
            int r = idx >> 5;
            int rem = idx & 31;
            int part = rem >> 4;
            int c = rem & 15;
            cp16(sb + part * (128 * FROWB) + r * FROWB + c * 16,
                 gq + ((size_t)(q0 + r)) * 256 + part * 128 + c * 8);
        }
        cp_commit();
        cp_wait<0>();
        __syncthreads();
    }

    uint32_t qh[8][4], qlr[8][4];
    {
        int r  = w * 16 + (lane & 15);
        int cb = ((lane >> 4) & 1) * 16;
#pragma unroll
        for (int c = 0; c < 8; ++c) {
            ldsm_x4(qh[c][0], qh[c][1], qh[c][2], qh[c][3],
                    sb + r * FROWB + c * 32 + cb);
            ldsm_x4(qlr[c][0], qlr[c][1], qlr[c][2], qlr[c][3],
                    sb + 128 * FROWB + r * FROWB + c * 32 + cb);
        }
    }
    __syncthreads();

    auto load_kv = [&](int slot, int kt) {
        const uint32_t st = sb + slot * FSTAGE;
        const int k0 = kt * 64;
#pragma unroll
        for (int i = 0; i < 16; ++i) {
            int idx = tid + i * 256;
            int tile = idx >> 10;
            int rem = idx & 1023;
            int r = rem >> 4;
            int c = rem & 15;
            const __nv_bfloat16* src;
            if (tile == 0)      src = gk + ((size_t)(k0 + r)) * 256 +       c * 8;
            else if (tile == 1) src = gk + ((size_t)(k0 + r)) * 256 + 128 + c * 8;
            else if (tile == 2) src = gv + ((size_t)(k0 + r)) * 256 +       c * 8;
            else                src = gv + ((size_t)(k0 + r)) * 256 + 128 + c * 8;
            cp16(st + tile * FTILE + r * FROWB + c * 16, src);
        }
    };

    load_kv(0, 0); cp_commit();
    load_kv(1, 1); cp_commit();

    float m_g = -1e30f, m_g8 = -1e30f, l_g = 0.f, l_g8 = 0.f;
    float o[16][4];
#pragma unroll
    for (int t = 0; t < 16; ++t)
#pragma unroll
        for (int q = 0; q < 4; ++q) o[t][q] = 0.f;

    const int b_row = (lane & 7) + ((lane >> 4) & 1) * 8;
    const int b_k   = ((lane >> 3) & 1) * 16;
    const int v_row = (lane & 7) + ((lane >> 3) & 1) * 8;
    const int v_cb  = ((lane >> 4) & 1) * 16;
    const int row_g = q0 + w * 16 + g;

    for (int kt = 0; kt < nkt; ++kt) {
        const int s = kt & 1;
        const int k0 = kt * 64;
        cp_wait<1>();
        __syncthreads();

        if (k0 <= q0 + w * 16 + 15) {
            const uint32_t sKh = sb + s * FSTAGE;
            const uint32_t sKl = sKh + FTILE;
            const uint32_t sVh = sKh + 2 * FTILE;
            const uint32_t sVl = sKh + 3 * FTILE;

            float s4[8][4];
#pragma unroll
            for (int j = 0; j < 8; ++j)
#pragma unroll
                for (int q = 0; q < 4; ++q) s4[j][q] = 0.f;

#pragma unroll
            for (int c8 = 0; c8 < 8; ++c8) {
                uint32_t bb[8][2];
#pragma unroll
                for (int np = 0; np < 4; ++np) {
                    uint32_t r0, r1, r2, r3;
                    ldsm_x4(r0, r1, r2, r3,
                            sKh + (np * 16 + b_row) * FROWB + c8 * 32 + b_k);
                    bb[2*np][0] = r0; bb[2*np][1] = r1;
                    bb[2*np+1][0] = r2; bb[2*np+1][1] = r3;
                }
#pragma unroll
                for (int j = 0; j < 8; ++j)
                    mma_bf16(s4[j][0], s4[j][1], s4[j][2], s4[j][3],
                             qh[c8][0], qh[c8][1], qh[c8][2], qh[c8][3],
                             bb[j][0], bb[j][1]);
#pragma unroll
                for (int j = 0; j < 8; ++j)
                    mma_bf16(s4[j][0], s4[j][1], s4[j][2], s4[j][3],
                             qlr[c8][0], qlr[c8][1], qlr[c8][2], qlr[c8][3],
                             bb[j][0], bb[j][1]);
#pragma unroll
                for (int np = 0; np < 4; ++np) {
                    uint32_t r0, r1, r2, r3;
                    ldsm_x4(r0, r1, r2, r3,
                            sKl + (np * 16 + b_row) * FROWB + c8 * 32 + b_k);
                    bb[2*np][0] = r0; bb[2*np][1] = r1;
                    bb[2*np+1][0] = r2; bb[2*np+1][1] = r3;
                }
#pragma unroll
                for (int j = 0; j < 8; ++j)
                    mma_bf16(s4[j][0], s4[j][1], s4[j][2], s4[j][3],
                             qh[c8][0], qh[c8][1], qh[c8][2], qh[c8][3],
                             bb[j][0], bb[j][1]);
            }

            const bool diag = (k0 + 63 > q0 + w * 16);
#pragma unroll
            for (int j = 0; j < 8; ++j) {
                int col = k0 + j * 8 + 2 * ti;
                s4[j][0] *= scl2; s4[j][1] *= scl2;
                s4[j][2] *= scl2; s4[j][3] *= scl2;
                if (diag) {
                    if (col     > row_g)     s4[j][0] = -1e30f;
                    if (col + 1 > row_g)     s4[j][1] = -1e30f;
                    if (col     > row_g + 8) s4[j][2] = -1e30f;
                    if (col + 1 > row_g + 8) s4[j][3] = -1e30f;
                }
            }

            float tm_g = -1e30f, tm_g8 = -1e30f;
#pragma unroll
            for (int j = 0; j < 8; ++j) {
                tm_g  = fmaxf(tm_g,  fmaxf(s4[j][0], s4[j][1]));
                tm_g8 = fmaxf(tm_g8, fmaxf(s4[j][2], s4[j][3]));
            }
            tm_g  = fmaxf(tm_g,  __shfl_xor_sync(0xffffffffu, tm_g, 1));
            tm_g  = fmaxf(tm_g,  __shfl_xor_sync(0xffffffffu, tm_g, 2));
            tm_g8 = fmaxf(tm_g8, __shfl_xor_sync(0xffffffffu, tm_g8, 1));
            tm_g8 = fmaxf(tm_g8, __shfl_xor_sync(0xffffffffu, tm_g8, 2));

            float mn_g  = fmaxf(m_g,  tm_g);
            float mn_g8 = fmaxf(m_g8, tm_g8);
            float corr_g  = fexp2(m_g  - mn_g);
            float corr_g8 = fexp2(m_g8 - mn_g8);

            float sum_g = 0.f, sum_g8 = 0.f;
#pragma unroll
            for (int j = 0; j < 8; ++j) {
                s4[j][0] = fexp2(s4[j][0] - mn_g);
                s4[j][1] = fexp2(s4[j][1] - mn_g);
                s4[j][2] = fexp2(s4[j][2] - mn_g8);
                s4[j][3] = fexp2(s4[j][3] - mn_g8);
                sum_g  += s4[j][0] + s4[j][1];
                sum_g8 += s4[j][2] + s4[j][3];
            }
            sum_g  += __shfl_xor_sync(0xffffffffu, sum_g, 1);
            sum_g  += __shfl_xor_sync(0xffffffffu, sum_g, 2);
            sum_g8 += __shfl_xor_sync(0xffffffffu, sum_g8, 1);
            sum_g8 += __shfl_xor_sync(0xffffffffu, sum_g8, 2);

            l_g  = l_g  * corr_g  + sum_g;   m_g  = mn_g;
            l_g8 = l_g8 * corr_g8 + sum_g8;  m_g8 = mn_g8;

#pragma unroll
            for (int t = 0; t < 16; ++t) {
                o[t][0] *= corr_g;  o[t][1] *= corr_g;
                o[t][2] *= corr_g8; o[t][3] *= corr_g8;
            }

#pragma unroll
            for (int c = 0; c < 4; ++c) {
                uint32_t aPh[4], aPl[4];
                aPh[0] = pack_bf16(s4[2*c][0],   s4[2*c][1]);
                aPh[1] = pack_bf16(s4[2*c][2],   s4[2*c][3]);
                aPh[2] = pack_bf16(s4[2*c+1][0], s4[2*c+1][1]);
                aPh[3] = pack_bf16(s4[2*c+1][2], s4[2*c+1][3]);
                {
                    float2 u;
                    u = unpack_bf16(aPh[0]);
                    aPl[0] = pack_bf16(s4[2*c][0] - u.x,   s4[2*c][1] - u.y);
                    u = unpack_bf16(aPh[1]);
                    aPl[1] = pack_bf16(s4[2*c][2] - u.x,   s4[2*c][3] - u.y);
                    u = unpack_bf16(aPh[2]);
                    aPl[2] = pack_bf16(s4[2*c+1][0] - u.x, s4[2*c+1][1] - u.y);
                    u = unpack_bf16(aPh[3]);
                    aPl[3] = pack_bf16(s4[2*c+1][2] - u.x, s4[2*c+1][3] - u.y);
                }
#pragma unroll
                for (int dh = 0; dh < 2; ++dh) {
                    uint32_t bv[8][2];
#pragma unroll
                    for (int dd = 0; dd < 4; ++dd) {
                        uint32_t r0, r1, r2, r3;
                        ldsm_x4_t(r0, r1, r2, r3,
                                  sVh + (c * 16 + v_row) * FROWB
                                      + (dh * 4 + dd) * 32 + v_cb);
                        bv[2*dd][0] = r0; bv[2*dd][1] = r1;
                        bv[2*dd+1][0] = r2; bv[2*dd+1][1] = r3;
                    }
#pragma unroll
                    for (int tt = 0; tt < 8; ++tt) {
                        int t = dh * 8 + tt;
                        mma_bf16(o[t][0], o[t][1], o[t][2], o[t][3],
                                 aPh[0], aPh[1], aPh[2], aPh[3],
                                 bv[tt][0], bv[tt][1]);
                        mma_bf16(o[t][0], o[t][1], o[t][2], o[t][3],
                                 aPl[0], aPl[1], aPl[2], aPl[3],
                                 bv[tt][0], bv[tt][1]);
                    }
#pragma unroll
                    for (int dd = 0; dd < 4; ++dd) {
                        uint32_t r0, r1, r2, r3;
                        ldsm_x4_t(r0, r1, r2, r3,
                                  sVl + (c * 16 + v_row) * FROWB
                                      + (dh * 4 + dd) * 32 + v_cb);
                        bv[2*dd][0] = r0; bv[2*dd][1] = r1;
                        bv[2*dd+1][0] = r2; bv[2*dd+1][1] = r3;
                    }
#pragma unroll
                    for (int tt = 0; tt < 8; ++tt) {
                        int t = dh * 8 + tt;
                        mma_bf16(o[t][0], o[t][1], o[t][2], o[t][3],
                                 aPh[0], aPh[1], aPh[2], aPh[3],
                                 bv[tt][0], bv[tt][1]);
                    }
                }
            }
        }

        __syncthreads();
        if (kt + 2 < nkt) load_kv(s, kt + 2);
        cp_commit();                  // unconditional: keeps wait<1> sound at tail
    }

    const float inv_g  = 1.f / l_g;
    const float inv_g8 = 1.f / l_g8;
    const size_t row_i = (size_t)(b * SEQ + q0 + w * 16 + g);
    __nv_bfloat16* a0 = Aout + row_i * KSPLIT + h * HD;
    __nv_bfloat16* a8 = a0 + (size_t)8 * KSPLIT;
#pragma unroll
    for (int t = 0; t < 16; ++t) {
        int d = t * 8 + 2 * ti;
        {
            float v0 = o[t][0] * inv_g, v1 = o[t][1] * inv_g;
            __nv_bfloat16 h0 = __float2bfloat16(v0);
            __nv_bfloat16 h1 = __float2bfloat16(v1);
            __nv_bfloat16 l0 = __float2bfloat16(v0 - __bfloat162float(h0));
            __nv_bfloat16 l1 = __float2bfloat16(v1 - __bfloat162float(h1));
            __nv_bfloat162 hp = __halves2bfloat162(h0, h1);
            *(__nv_bfloat162*)(a0 + d)        = hp;
            *(__nv_bfloat162*)(a0 + 2048 + d) = __halves2bfloat162(l0, l1);
            *(__nv_bfloat162*)(a0 + 4096 + d) = hp;
        }
        {
            float v0 = o[t][2] * inv_g8, v1 = o[t][3] * inv_g8;
            __nv_bfloat16 h0 = __float2bfloat16(v0);
            __nv_bfloat16 h1 = __float2bfloat16(v1);
            __nv_bfloat16 l0 = __float2bfloat16(v0 - __bfloat162float(h0));
            __nv_bfloat16 l1 = __float2bfloat16(v1 - __bfloat162float(h1));
            __nv_bfloat162 hp = __halves2bfloat162(h0, h1);
            *(__nv_bfloat162*)(a8 + d)        = hp;
            *(__nv_bfloat162*)(a8 + 2048 + d) = __halves2bfloat162(l0, l1);
            *(__nv_bfloat162*)(a8 + 4096 + d) = hp;
        }
    }
}

// ---------------------------------------------------------------------------
// Host side
// ---------------------------------------------------------------------------
extern "C" void kernel_launch(void* const* d_in, const int* in_sizes, int n_in,
                              void* d_out, int out_size)
{
    (void)in_sizes; (void)n_in; (void)out_size;
    const float* hs      = (const float*)d_in[0];
    const float* w_qkv   = (const float*)d_in[1];
    const float* b_qkv   = (const float*)d_in[2];
    const float* w_dense = (const float*)d_in[3];
    const float* b_dense = (const float*)d_in[4];
    float* out = (float*)d_out;

    void *p_ab, *p_bqkv, *p_bdense, *p_hs;
    cudaGetSymbolAddress(&p_ab, g_ab);
    cudaGetSymbolAddress(&p_bqkv, g_bqkv);
    cudaGetSymbolAddress(&p_bdense, g_bdense);
    cudaGetSymbolAddress(&p_hs, g_hsplit);

    static bool attr_done = false;
    if (!attr_done) {
        cudaFuncSetAttribute(gemm_mma_kernel<0>,
                             cudaFuncAttributeMaxDynamicSharedMemorySize, GEMM_SMEM);
        cudaFuncSetAttribute(gemm_mma_kernel<1>,
                             cudaFuncAttributeMaxDynamicSharedMemorySize, GEMM_SMEM);
        cudaFuncSetAttribute(flash_mma_kernel,
                             cudaFuncAttributeMaxDynamicSharedMemorySize, FLASH_SMEM);
        attr_done = true;
    }

    // 1) split inputs to bf16 hi/lo
    {
        int nv = MROWS * HID / 4;
        split_kernel<<<(nv + 255) / 256, 256>>>((const float4*)hs,
                                                (__nv_bfloat162*)p_ab, nv, 0);
        nv = QKVN * HID / 4;
        split_kernel<<<(nv + 255) / 256, 256>>>((const float4*)w_qkv,
                                                (__nv_bfloat162*)p_bqkv, nv, 1);
        nv = HID * HID / 4;
        split_kernel<<<(nv + 255) / 256, 256>>>((const float4*)w_dense,
                                                (__nv_bfloat162*)p_bdense, nv, 1);
    }

    // 2) QKV projection, fused per-head hi/lo split epilogue
    {
        dim3 g(QKVN / 256, MROWS / 128);
        gemm_mma_kernel<1><<<g, 256, GEMM_SMEM>>>(
            (const __nv_bfloat16*)p_ab, (const __nv_bfloat16*)p_bqkv,
            b_qkv, nullptr, (__nv_bfloat16*)p_hs, QKVN);
    }

    // 3) flash attention (HMMA), fused split epilogue into g_ab
    {
        flash_mma_kernel<<<1024, 256, FLASH_SMEM>>>(
            (const __nv_bfloat16*)p_hs, (__nv_bfloat16*)p_ab);
    }

    // 4) dense projection
    {
        dim3 g(HID / 256, MROWS / 128);
        gemm_mma_kernel<0><<<g, 256, GEMM_SMEM>>>(
            (const __nv_bfloat16*)p_ab, (const __nv_bfloat16*)p_bdense,
            b_dense, out, nullptr, HID);
    }
}

// round 7
// speedup vs baseline: 1.7222x; 1.4960x over previous
#include <cuda_runtime.h>
#include <cuda_fp16.h>
#include <math.h>
#include <stdint.h>

#define HID   2048
#define NH    16
#define HD    128
#define BATCH 4
#define SEQ   2048
#define MROWS (BATCH*SEQ)     // 8192
#define QKVN  (3*HID)         // 6144
#define KA    4096            // A-side K' = [hi|lo]
#define KB    2048            // B-side K  (plain fp16, wrapped)

// ---------------------------------------------------------------------------
// Scratch
// ---------------------------------------------------------------------------
__device__ __align__(1024) __half g_ab[(size_t)MROWS * KA];     // A' [hi|lo]
__device__ __align__(1024) __half g_bqkv[(size_t)QKVN * KB];    // w_qkv fp16
__device__ __align__(1024) __half g_bdense[(size_t)HID * KB];   // w_dense fp16
// per-head layout: [sel(q,k,v)][b][h][s][hi128|lo128] (lo used only for Q)
__device__ __align__(1024) __half g_hsplit[(size_t)3 * BATCH * NH * SEQ * 256];

// ---------------------------------------------------------------------------
// PTX helpers (portable sm_80+)
// ---------------------------------------------------------------------------
__device__ __forceinline__ uint32_t smem_u32(const void* p) {
    uint32_t a;
    asm("{ .reg .u64 t; cvta.to.shared.u64 t, %1; cvt.u32.u64 %0, t; }"
        : "=r"(a) : "l"(p));
    return a;
}
__device__ __forceinline__ void cp16(uint32_t s, const void* g) {
    asm volatile("cp.async.cg.shared.global [%0], [%1], 16;" :: "r"(s), "l"(g));
}
__device__ __forceinline__ void cp_commit() {
    asm volatile("cp.async.commit_group;" ::: "memory");
}
template<int N> __device__ __forceinline__ void cp_wait() {
    asm volatile("cp.async.wait_group %0;" :: "n"(N) : "memory");
}
__device__ __forceinline__ void ldsm_x4(uint32_t& r0, uint32_t& r1,
                                        uint32_t& r2, uint32_t& r3, uint32_t addr) {
    asm volatile("ldmatrix.sync.aligned.m8n8.x4.shared.b16 {%0,%1,%2,%3}, [%4];"
                 : "=r"(r0), "=r"(r1), "=r"(r2), "=r"(r3) : "r"(addr));
}
__device__ __forceinline__ void ldsm_x4_t(uint32_t& r0, uint32_t& r1,
                                          uint32_t& r2, uint32_t& r3, uint32_t addr) {
    asm volatile("ldmatrix.sync.aligned.m8n8.x4.trans.shared.b16 {%0,%1,%2,%3}, [%4];"
                 : "=r"(r0), "=r"(r1), "=r"(r2), "=r"(r3) : "r"(addr));
}
__device__ __forceinline__ void mma_f16(float& d0, float& d1, float& d2, float& d3,
                                        uint32_t a0, uint32_t a1, uint32_t a2, uint32_t a3,
                                        uint32_t b0, uint32_t b1) {
    asm volatile(
        "mma.sync.aligned.m16n8k16.row.col.f32.f16.f16.f32 "
        "{%0,%1,%2,%3}, {%4,%5,%6,%7}, {%8,%9}, {%0,%1,%2,%3};"
        : "+f"(d0), "+f"(d1), "+f"(d2), "+f"(d3)
        : "r"(a0), "r"(a1), "r"(a2), "r"(a3), "r"(b0), "r"(b1));
}
__device__ __forceinline__ uint32_t pack_f16(float a, float b) {
    __half2 t = __floats2half2_rn(a, b);
    return *(uint32_t*)&t;
}
__device__ __forceinline__ float2 unpack_f16(uint32_t u) {
    __half2 t = *(__half2*)&u;
    return __half22float2(t);
}
// MUFU-free exp2 (FMA/ALU pipes only). Valid for x <= ~0; err ~2e-6.
__device__ __forceinline__ float fexp2(float x) {
    x = fmaxf(x, -126.f);
    float t  = __fadd_rn(x, 12582912.f);
    int   i  = __float_as_int(t) << 23;
    float xf = x - __fsub_rn(t, 12582912.f);
    float p  = 1.3333558e-3f;
    p = fmaf(p, xf, 9.6181291e-3f);
    p = fmaf(p, xf, 5.5504109e-2f);
    p = fmaf(p, xf, 2.4022651e-1f);
    p = fmaf(p, xf, 6.9314718e-1f);
    p = fmaf(p, xf, 1.0f);
    return __int_as_float(i + __float_as_int(p));
}

// ---------------------------------------------------------------------------
// Split kernels
//   mode 0 (A side): fp32 [R,2048] -> fp16 [R,4096] as [hi | lo]
//   mode 1 (B side): fp32 [R,2048] -> fp16 [R,2048] plain convert
// ---------------------------------------------------------------------------
__global__ __launch_bounds__(256)
void split_kernel(const float4* __restrict__ in, __half2* __restrict__ out,
                  int nvec, int mode)
{
    int i = blockIdx.x * blockDim.x + threadIdx.x;
    if (i >= nvec) return;
    float4 v = in[i];
    int r = i >> 9;            // 512 float4 per 2048-col row
    int c = (i & 511) << 2;

    __half h0 = __float2half_rn(v.x);
    __half h1 = __float2half_rn(v.y);
    __half h2 = __float2half_rn(v.z);
    __half h3 = __float2half_rn(v.w);
    __half2 hA = __halves2half2(h0, h1);
    __half2 hB = __halves2half2(h2, h3);

    if (mode == 0) {
        __half l0 = __float2half_rn(v.x - __half2float(h0));
        __half l1 = __float2half_rn(v.y - __half2float(h1));
        __half l2 = __float2half_rn(v.z - __half2float(h2));
        __half l3 = __float2half_rn(v.w - __half2float(h3));
        size_t base = (size_t)r * 2048 + (c >> 1);   // row = 4096 fp16 = 2048 half2
        out[base]        = hA; out[base + 1]    = hB;
        out[base + 1024] = __halves2half2(l0, l1);
        out[base + 1025] = __halves2half2(l2, l3);
    } else {
        size_t base = (size_t)r * 1024 + (c >> 1);   // row = 2048 fp16
        out[base] = hA; out[base + 1] = hB;
    }
}

// ---------------------------------------------------------------------------
// fp16 HMMA GEMM: C = A'[M,4096] @ (B[N,2048] wrapped)^T + bias
// K-chunk 64, 3 stages, fragment double buffering. CTA 128x256, 8 warps.
//   QKV_EPI=0: fp32 + bias -> C
//   QKV_EPI=1: per-head fp16 into H (hi always; lo only for sel==0 i.e. Q)
// ---------------------------------------------------------------------------
#define NCHUNK  (KA / 64)          // 64
#define GSTAGES 3
#define ROWB    144
#define A_BYTES (128 * ROWB)
#define B_BYTES (256 * ROWB)
#define STAGE_B (A_BYTES + B_BYTES)
#define GEMM_SMEM (GSTAGES * STAGE_B)   // 165888

template<int QKV_EPI>
__global__ __launch_bounds__(256, 1)
void gemm_mma_kernel(const __half* __restrict__ A,
                     const __half* __restrict__ B,
                     const float* __restrict__ bias,
                     float* __restrict__ C,
                     __half* __restrict__ H,
                     int N)
{
    extern __shared__ __align__(128) char smem[];
    const uint32_t sb = smem_u32(smem);

    const int tid  = threadIdx.x;
    const int wid  = tid >> 5;
    const int lane = tid & 31;
    const int wm   = wid & 1;
    const int wn   = wid >> 1;
    const int m0   = blockIdx.y * 128;
    const int n0   = blockIdx.x * 256;

    const int a_row = (lane & 7) + ((lane >> 3) & 1) * 8;
    const int a_k8  = (lane >> 4) & 1;
    const int b_nrw = (lane & 7) + ((lane >> 4) & 1) * 8;
    const int b_k8  = (lane >> 3) & 1;

    float acc[4][8][4];
#pragma unroll
    for (int i = 0; i < 4; ++i)
#pragma unroll
        for (int j = 0; j < 8; ++j)
#pragma unroll
            for (int q = 0; q < 4; ++q) acc[i][j][q] = 0.f;

    auto load_stage = [&](int slot, int kk) {
        const uint32_t sa  = sb + slot * STAGE_B;
        const uint32_t sbb = sa + A_BYTES;
        const __half* Ak = A + (size_t)m0 * KA + kk * 64;
        const __half* Bk = B + (size_t)n0 * KB + (kk & 31) * 64;  // wrap mod 2048
#pragma unroll
        for (int i = 0; i < 4; ++i) {
            int idx = tid + i * 256;
            int r = idx >> 3, c = idx & 7;
            cp16(sa + r * ROWB + c * 16, Ak + (size_t)r * KA + c * 8);
        }
#pragma unroll
        for (int i = 0; i < 8; ++i) {
            int idx = tid + i * 256;
            int r = idx >> 3, c = idx & 7;
            cp16(sbb + r * ROWB + c * 16, Bk + (size_t)r * KB + c * 8);
        }
    };

    load_stage(0, 0); cp_commit();
    load_stage(1, 1); cp_commit();

    uint32_t af[2][4][4];
    uint32_t bfr[2][8][2];

    for (int k = 0; k < NCHUNK; ++k) {
        const int s = k % GSTAGES;
        cp_wait<1>();
        __syncthreads();

        if (k + 2 < NCHUNK) load_stage((k + 2) % GSTAGES, k + 2);
        cp_commit();

        const uint32_t sa  = sb + s * STAGE_B + (wm * 64) * ROWB;
        const uint32_t sbb = sb + s * STAGE_B + A_BYTES + (wn * 64) * ROWB;

        auto load_frag = [&](int buf, int kkv) {
#pragma unroll
            for (int mt = 0; mt < 4; ++mt)
                ldsm_x4(af[buf][mt][0], af[buf][mt][1],
                        af[buf][mt][2], af[buf][mt][3],
                        sa + (mt * 16 + a_row) * ROWB + kkv * 32 + a_k8 * 16);
#pragma unroll
            for (int np = 0; np < 4; ++np) {
                uint32_t r0, r1, r2, r3;
                ldsm_x4(r0, r1, r2, r3,
                        sbb + (np * 16 + b_nrw) * ROWB + kkv * 32 + b_k8 * 16);
                bfr[buf][2*np][0] = r0;   bfr[buf][2*np][1] = r1;
                bfr[buf][2*np+1][0] = r2; bfr[buf][2*np+1][1] = r3;
            }
        };

        load_frag(0, 0);
#pragma unroll
        for (int kkv = 0; kkv < 4; ++kkv) {
            const int cur = kkv & 1;
            if (kkv < 3) load_frag(cur ^ 1, kkv + 1);
#pragma unroll
            for (int mt = 0; mt < 4; ++mt)
#pragma unroll
                for (int nt = 0; nt < 8; ++nt)
                    mma_f16(acc[mt][nt][0], acc[mt][nt][1],
                            acc[mt][nt][2], acc[mt][nt][3],
                            af[cur][mt][0], af[cur][mt][1],
                            af[cur][mt][2], af[cur][mt][3],
                            bfr[cur][nt][0], bfr[cur][nt][1]);
        }
    }

    const int g  = lane >> 2;
    const int ti = lane & 3;

    if (QKV_EPI == 0) {
#pragma unroll
        for (int mt = 0; mt < 4; ++mt) {
            const int row = m0 + wm * 64 + mt * 16 + g;
#pragma unroll
            for (int nt = 0; nt < 8; ++nt) {
                const int col = n0 + wn * 64 + nt * 8 + ti * 2;
                float2 bv = *(const float2*)(bias + col);
                float2 o0 = make_float2(acc[mt][nt][0] + bv.x, acc[mt][nt][1] + bv.y);
                float2 o1 = make_float2(acc[mt][nt][2] + bv.x, acc[mt][nt][3] + bv.y);
                *(float2*)(C + (size_t)row * N + col)       = o0;
                *(float2*)(C + (size_t)(row + 8) * N + col) = o1;
            }
        }
    } else {
#pragma unroll
        for (int mt = 0; mt < 4; ++mt) {
            const int row = m0 + wm * 64 + mt * 16 + g;
            const int b   = row >> 11;
            const int sidx = row & 2047;
#pragma unroll
            for (int nt = 0; nt < 8; ++nt) {
                const int col = n0 + wn * 64 + nt * 8 + ti * 2;
                const int sel = col >> 11;
                const int hh  = (col >> 7) & 15;
                const int d   = col & 127;
                float2 bv = *(const float2*)(bias + col);
                size_t base = ((((size_t)sel * BATCH + b) * NH + hh) * SEQ + sidx) * 256 + d;
#pragma unroll
                for (int half = 0; half < 2; ++half) {
                    float v0 = acc[mt][nt][half * 2 + 0] + bv.x;
                    float v1 = acc[mt][nt][half * 2 + 1] + bv.y;
                    __half h0 = __float2half_rn(v0);
                    __half h1 = __float2half_rn(v1);
                    size_t bb = base + (size_t)half * 8 * 256;
                    *(__half2*)(H + bb) = __halves2half2(h0, h1);
                    if (sel == 0) {  // lo needed only for Q
                        __half l0 = __float2half_rn(v0 - __half2float(h0));
                        __half l1 = __float2half_rn(v1 - __half2float(h1));
                        *(__half2*)(H + bb + 128) = __halves2half2(l0, l1);
                    }
                }
            }
        }
    }
}

// ---------------------------------------------------------------------------
// Flash attention, fp16 HMMA, 2-term precision, causal, MUFU-free softmax.
// Bq=128 (8 warps x 16 rows), Bk=64, D=128. S = (Qh+Ql)Kh; O = (Ph+Pl)Vh.
// Epilogue writes g_ab [hi|lo] fp16 (K'=4096) for the dense GEMM.
// ---------------------------------------------------------------------------
#define FROWB 272
#define FTILE (64 * FROWB)
#define FSTAGE (2 * FTILE)              // Kh + Vh only
#define FLASH_SMEM (2 * FSTAGE)         // 69632

__global__ __launch_bounds__(256, 1)
void flash_mma_kernel(const __half* __restrict__ gs,
                      __half* __restrict__ Aout)
{
    extern __shared__ __align__(128) char smem[];
    const uint32_t sb = smem_u32(smem);

    const int bid = blockIdx.x;
    const int qt  = 15 - (bid >> 6);
    const int sub = bid & 63;
    const int h   = sub & 15;
    const int b   = sub >> 4;
    const int q0  = qt * 128;
    const int nkt = 2 * qt + 2;

    const int tid  = threadIdx.x;
    const int w    = tid >> 5;
    const int lane = tid & 31;
    const int g    = lane >> 2;
    const int ti   = lane & 3;
    const float scl2 = 0.08838834764831845f * 1.4426950408889634f;

    const __half* gq = gs + (((size_t)0 * BATCH + b) * NH + h) * SEQ * 256;
    const __half* gk = gs + (((size_t)1 * BATCH + b) * NH + h) * SEQ * 256;
    const __half* gv = gs + (((size_t)2 * BATCH + b) * NH + h) * SEQ * 256;

    // ---- stage Q (hi+lo) through smem (fits exactly in FLASH_SMEM) ----
    {
#pragma unroll
        for (int i = 0; i < 16; ++i) {
            int idx = tid + i * 256;
            int r = idx >> 5;
            int rem = idx & 31;
            int part = rem >> 4;
            int c = rem & 15;
            cp16(sb + part * (128 * FROWB) + r * FROWB + c * 16,
                 gq + ((size_t)(q0 + r)) * 256 + part * 128 + c * 8);
        }
        cp_commit();
        cp_wait<0>();
        __syncthreads();
    }

    uint32_t qh[8][4], qlr[8][4];
    {
        int r  = w * 16 + (lane & 15);
        int cb = ((lane >> 4) & 1) * 16;
#pragma unroll
        for (int c = 0; c < 8; ++c) {
            ldsm_x4(qh[c][0], qh[c][1], qh[c][2], qh[c][3],
                    sb + r * FROWB + c * 32 + cb);
            ldsm_x4(qlr[c][0], qlr[c][1], qlr[c][2], qlr[c][3],
                    sb + 128 * FROWB + r * FROWB + c * 32 + cb);
        }
    }
    __syncthreads();

    // K/V loader: Kh, Vh tiles only (8 cp16/thread)
    auto load_kv = [&](int slot, int kt) {
        const uint32_t st = sb + slot * FSTAGE;
        const int k0 = kt * 64;
#pragma unroll
        for (int i = 0; i < 8; ++i) {
            int idx = tid + i * 256;          // < 2048
            int tile = idx >> 10;             // 0..1
            int rem = idx & 1023;
            int r = rem >> 4;
            int c = rem & 15;
            const __half* src = (tile == 0 ? gk : gv)
                              + ((size_t)(k0 + r)) * 256 + c * 8;
            cp16(st + tile * FTILE + r * FROWB + c * 16, src);
        }
    };

    load_kv(0, 0); cp_commit();
    load_kv(1, 1); cp_commit();

    float m_g = -1e30f, m_g8 = -1e30f, l_g = 0.f, l_g8 = 0.f;
    float o[16][4];
#pragma unroll
    for (int t = 0; t < 16; ++t)
#pragma unroll
        for (int q = 0; q < 4; ++q) o[t][q] = 0.f;

    const int b_row = (lane & 7) + ((lane >> 4) & 1) * 8;
    const int b_k   = ((lane >> 3) & 1) * 16;
    const int v_row = (lane & 7) + ((lane >> 3) & 1) * 8;
    const int v_cb  = ((lane >> 4) & 1) * 16;
    const int row_g = q0 + w * 16 + g;

    for (int kt = 0; kt < nkt; ++kt) {
        const int s = kt & 1;
        const int k0 = kt * 64;
        cp_wait<1>();
        __syncthreads();

        if (k0 <= q0 + w * 16 + 15) {
            const uint32_t sKh = sb + s * FSTAGE;
            const uint32_t sVh = sKh + FTILE;

            float s4[8][4];
#pragma unroll
            for (int j = 0; j < 8; ++j)
#pragma unroll
                for (int q = 0; q < 4; ++q) s4[j][q] = 0.f;

#pragma unroll
            for (int c8 = 0; c8 < 8; ++c8) {
                uint32_t bb[8][2];
#pragma unroll
                for (int np = 0; np < 4; ++np) {
                    uint32_t r0, r1, r2, r3;
                    ldsm_x4(r0, r1, r2, r3,
                            sKh + (np * 16 + b_row) * FROWB + c8 * 32 + b_k);
                    bb[2*np][0] = r0; bb[2*np][1] = r1;
                    bb[2*np+1][0] = r2; bb[2*np+1][1] = r3;
                }
#pragma unroll
                for (int j = 0; j < 8; ++j)
                    mma_f16(s4[j][0], s4[j][1], s4[j][2], s4[j][3],
                            qh[c8][0], qh[c8][1], qh[c8][2], qh[c8][3],
                            bb[j][0], bb[j][1]);
#pragma unroll
                for (int j = 0; j < 8; ++j)
                    mma_f16(s4[j][0], s4[j][1], s4[j][2], s4[j][3],
                            qlr[c8][0], qlr[c8][1], qlr[c8][2], qlr[c8][3],
                            bb[j][0], bb[j][1]);
            }

            const bool diag = (k0 + 63 > q0 + w * 16);
#pragma unroll
            for (int j = 0; j < 8; ++j) {
                int col = k0 + j * 8 + 2 * ti;
                s4[j][0] *= scl2; s4[j][1] *= scl2;
                s4[j][2] *= scl2; s4[j][3] *= scl2;
                if (diag) {
                    if (col     > row_g)     s4[j][0] = -1e30f;
                    if (col + 1 > row_g)     s4[j][1] = -1e30f;
                    if (col     > row_g + 8) s4[j][2] = -1e30f;
                    if (col + 1 > row_g + 8) s4[j][3] = -1e30f;
                }
            }

            float tm_g = -1e30f, tm_g8 = -1e30f;
#pragma unroll
            for (int j = 0; j < 8; ++j) {
                tm_g  = fmaxf(tm_g,  fmaxf(s4[j][0], s4[j][1]));
                tm_g8 = fmaxf(tm_g8, fmaxf(s4[j][2], s4[j][3]));
            }
            tm_g  = fmaxf(tm_g,  __shfl_xor_sync(0xffffffffu, tm_g, 1));
            tm_g  = fmaxf(tm_g,  __shfl_xor_sync(0xffffffffu, tm_g, 2));
            tm_g8 = fmaxf(tm_g8, __shfl_xor_sync(0xffffffffu, tm_g8, 1));
            tm_g8 = fmaxf(tm_g8, __shfl_xor_sync(0xffffffffu, tm_g8, 2));

            float mn_g  = fmaxf(m_g,  tm_g);
            float mn_g8 = fmaxf(m_g8, tm_g8);
            float corr_g  = fexp2(m_g  - mn_g);
            float corr_g8 = fexp2(m_g8 - mn_g8);

            float sum_g = 0.f, sum_g8 = 0.f;
#pragma unroll
            for (int j = 0; j < 8; ++j) {
                s4[j][0] = fexp2(s4[j][0] - mn_g);
                s4[j][1] = fexp2(s4[j][1] - mn_g);
                s4[j][2] = fexp2(s4[j][2] - mn_g8);
                s4[j][3] = fexp2(s4[j][3] - mn_g8);
                sum_g  += s4[j][0] + s4[j][1];
                sum_g8 += s4[j][2] + s4[j][3];
            }
            sum_g  += __shfl_xor_sync(0xffffffffu, sum_g, 1);
            sum_g  += __shfl_xor_sync(0xffffffffu, sum_g, 2);
            sum_g8 += __shfl_xor_sync(0xffffffffu, sum_g8, 1);
            sum_g8 += __shfl_xor_sync(0xffffffffu, sum_g8, 2);

            l_g  = l_g  * corr_g  + sum_g;   m_g  = mn_g;
            l_g8 = l_g8 * corr_g8 + sum_g8;  m_g8 = mn_g8;

#pragma unroll
            for (int t = 0; t < 16; ++t) {
                o[t][0] *= corr_g;  o[t][1] *= corr_g;
                o[t][2] *= corr_g8; o[t][3] *= corr_g8;
            }

#pragma unroll
            for (int c = 0; c < 4; ++c) {
                uint32_t aPh[4], aPl[4];
                aPh[0] = pack_f16(s4[2*c][0],   s4[2*c][1]);
                aPh[1] = pack_f16(s4[2*c][2],   s4[2*c][3]);
                aPh[2] = pack_f16(s4[2*c+1][0], s4[2*c+1][1]);
                aPh[3] = pack_f16(s4[2*c+1][2], s4[2*c+1][3]);
                {
                    float2 u;
                    u = unpack_f16(aPh[0]);
                    aPl[0] = pack_f16(s4[2*c][0] - u.x,   s4[2*c][1] - u.y);
                    u = unpack_f16(aPh[1]);
                    aPl[1] = pack_f16(s4[2*c][2] - u.x,   s4[2*c][3] - u.y);
                    u = unpack_f16(aPh[2]);
                    aPl[2] = pack_f16(s4[2*c+1][0] - u.x, s4[2*c+1][1] - u.y);
                    u = unpack_f16(aPh[3]);
                    aPl[3] = pack_f16(s4[2*c+1][2] - u.x, s4[2*c+1][3] - u.y);
                }
#pragma unroll
                for (int dh = 0; dh < 2; ++dh) {
                    uint32_t bv[8][2];
#pragma unroll
                    for (int dd = 0; dd < 4; ++dd) {
                        uint32_t r0, r1, r2, r3;
                        ldsm_x4_t(r0, r1, r2, r3,
                                  sVh + (c * 16 + v_row) * FROWB
                                      + (dh * 4 + dd) * 32 + v_cb);
                        bv[2*dd][0] = r0; bv[2*dd][1] = r1;
                        bv[2*dd+1][0] = r2; bv[2*dd+1][1] = r3;
                    }
#pragma unroll
                    for (int tt = 0; tt < 8; ++tt) {
                        int t = dh * 8 + tt;
                        mma_f16(o[t][0], o[t][1], o[t][2], o[t][3],
                                aPh[0], aPh[1], aPh[2], aPh[3],
                                bv[tt][0], bv[tt][1]);
                        mma_f16(o[t][0], o[t][1], o[t][2], o[t][3],
                                aPl[0], aPl[1], aPl[2], aPl[3],
                                bv[tt][0], bv[tt][1]);
                    }
                }
            }
        }

        __syncthreads();
        if (kt + 2 < nkt) load_kv(s, kt + 2);
        cp_commit();                  // unconditional: keeps wait<1> sound at tail
    }

    // ---- fused epilogue: normalize + fp16 hi/lo into g_ab [hi|lo] (K'=4096) ----
    const float inv_g  = 1.f / l_g;
    const float inv_g8 = 1.f / l_g8;
    const size_t row_i = (size_t)(b * SEQ + q0 + w * 16 + g);
    __half* a0 = Aout + row_i * KA + h * HD;
    __half* a8 = a0 + (size_t)8 * KA;
#pragma unroll
    for (int t = 0; t < 16; ++t) {
        int d = t * 8 + 2 * ti;
        {
            float v0 = o[t][0] * inv_g, v1 = o[t][1] * inv_g;
            __half h0 = __float2half_rn(v0);
            __half h1 = __float2half_rn(v1);
            __half l0 = __float2half_rn(v0 - __half2float(h0));
            __half l1 = __float2half_rn(v1 - __half2float(h1));
            *(__half2*)(a0 + d)        = __halves2half2(h0, h1);
            *(__half2*)(a0 + 2048 + d) = __halves2half2(l0, l1);
        }
        {
            float v0 = o[t][2] * inv_g8, v1 = o[t][3] * inv_g8;
            __half h0 = __float2half_rn(v0);
            __half h1 = __float2half_rn(v1);
            __half l0 = __float2half_rn(v0 - __half2float(h0));
            __half l1 = __float2half_rn(v1 - __half2float(h1));
            *(__half2*)(a8 + d)        = __halves2half2(h0, h1);
            *(__half2*)(a8 + 2048 + d) = __halves2half2(l0, l1);
        }
    }
}

// ---------------------------------------------------------------------------
// Host side
// ---------------------------------------------------------------------------
extern "C" void kernel_launch(void* const* d_in, const int* in_sizes, int n_in,
                              void* d_out, int out_size)
{
    (void)in_sizes; (void)n_in; (void)out_size;
    const float* hs      = (const float*)d_in[0];
    const float* w_qkv   = (const float*)d_in[1];
    const float* b_qkv   = (const float*)d_in[2];
    const float* w_dense = (const float*)d_in[3];
    const float* b_dense = (const float*)d_in[4];
    float* out = (float*)d_out;

    void *p_ab, *p_bqkv, *p_bdense, *p_hs;
    cudaGetSymbolAddress(&p_ab, g_ab);
    cudaGetSymbolAddress(&p_bqkv, g_bqkv);
    cudaGetSymbolAddress(&p_bdense, g_bdense);
    cudaGetSymbolAddress(&p_hs, g_hsplit);

    static bool attr_done = false;
    if (!attr_done) {
        cudaFuncSetAttribute(gemm_mma_kernel<0>,
                             cudaFuncAttributeMaxDynamicSharedMemorySize, GEMM_SMEM);
        cudaFuncSetAttribute(gemm_mma_kernel<1>,
                             cudaFuncAttributeMaxDynamicSharedMemorySize, GEMM_SMEM);
        cudaFuncSetAttribute(flash_mma_kernel,
                             cudaFuncAttributeMaxDynamicSharedMemorySize, FLASH_SMEM);
        attr_done = true;
    }

    // 1) splits: hs -> [hi|lo] A'; weights -> plain fp16
    {
        int nv = MROWS * HID / 4;
        split_kernel<<<(nv + 255) / 256, 256>>>((const float4*)hs,
                                                (__half2*)p_ab, nv, 0);
        nv = QKVN * HID / 4;
        split_kernel<<<(nv + 255) / 256, 256>>>((const float4*)w_qkv,
                                                (__half2*)p_bqkv, nv, 1);
        nv = HID * HID / 4;
        split_kernel<<<(nv + 255) / 256, 256>>>((const float4*)w_dense,
                                                (__half2*)p_bdense, nv, 1);
    }

    // 2) QKV projection, fused per-head fp16 split epilogue
    {
        dim3 g(QKVN / 256, MROWS / 128);
        gemm_mma_kernel<1><<<g, 256, GEMM_SMEM>>>(
            (const __half*)p_ab, (const __half*)p_bqkv,
            b_qkv, nullptr, (__half*)p_hs, QKVN);
    }

    // 3) flash attention (fp16 HMMA), fused [hi|lo] epilogue into g_ab
    {
        flash_mma_kernel<<<1024, 256, FLASH_SMEM>>>(
            (const __half*)p_hs, (__half*)p_ab);
    }

    // 4) dense projection
    {
        dim3 g(HID / 256, MROWS / 128);
        gemm_mma_kernel<0><<<g, 256, GEMM_SMEM>>>(
            (const __half*)p_ab, (const __half*)p_bdense,
            b_dense, out, nullptr, HID);
    }
}

// round 8
// speedup vs baseline: 2.7998x; 1.6257x over previous
#include <cuda_runtime.h>
#include <cuda_fp16.h>
#include <math.h>
#include <stdint.h>

#define HID   2048
#define NH    16
#define HD    128
#define BATCH 4
#define SEQ   2048
#define MROWS (BATCH*SEQ)     // 8192
#define QKVN  (3*HID)         // 6144
#define KGE   2048            // GEMM K (plain fp16 both sides)

// ---------------------------------------------------------------------------
// Scratch
// ---------------------------------------------------------------------------
__device__ __align__(1024) __half g_ab[(size_t)MROWS * KGE];    // A fp16
__device__ __align__(1024) __half g_bqkv[(size_t)QKVN * KGE];   // w_qkv fp16
__device__ __align__(1024) __half g_bdense[(size_t)HID * KGE];  // w_dense fp16
// per-head layout: [sel(q,k,v)][b][h][s][hi128|lo128] (lo used only for Q)
__device__ __align__(1024) __half g_hsplit[(size_t)3 * BATCH * NH * SEQ * 256];

// ---------------------------------------------------------------------------
// PTX helpers (portable sm_80+)
// ---------------------------------------------------------------------------
__device__ __forceinline__ uint32_t smem_u32(const void* p) {
    uint32_t a;
    asm("{ .reg .u64 t; cvta.to.shared.u64 t, %1; cvt.u32.u64 %0, t; }"
        : "=r"(a) : "l"(p));
    return a;
}
__device__ __forceinline__ void cp16(uint32_t s, const void* g) {
    asm volatile("cp.async.cg.shared.global [%0], [%1], 16;" :: "r"(s), "l"(g));
}
__device__ __forceinline__ void cp_commit() {
    asm volatile("cp.async.commit_group;" ::: "memory");
}
template<int N> __device__ __forceinline__ void cp_wait() {
    asm volatile("cp.async.wait_group %0;" :: "n"(N) : "memory");
}
__device__ __forceinline__ void ldsm_x4(uint32_t& r0, uint32_t& r1,
                                        uint32_t& r2, uint32_t& r3, uint32_t addr) {
    asm volatile("ldmatrix.sync.aligned.m8n8.x4.shared.b16 {%0,%1,%2,%3}, [%4];"
                 : "=r"(r0), "=r"(r1), "=r"(r2), "=r"(r3) : "r"(addr));
}
__device__ __forceinline__ void ldsm_x4_t(uint32_t& r0, uint32_t& r1,
                                          uint32_t& r2, uint32_t& r3, uint32_t addr) {
    asm volatile("ldmatrix.sync.aligned.m8n8.x4.trans.shared.b16 {%0,%1,%2,%3}, [%4];"
                 : "=r"(r0), "=r"(r1), "=r"(r2), "=r"(r3) : "r"(addr));
}
__device__ __forceinline__ void mma_f16(float& d0, float& d1, float& d2, float& d3,
                                        uint32_t a0, uint32_t a1, uint32_t a2, uint32_t a3,
                                        uint32_t b0, uint32_t b1) {
    asm volatile(
        "mma.sync.aligned.m16n8k16.row.col.f32.f16.f16.f32 "
        "{%0,%1,%2,%3}, {%4,%5,%6,%7}, {%8,%9}, {%0,%1,%2,%3};"
        : "+f"(d0), "+f"(d1), "+f"(d2), "+f"(d3)
        : "r"(a0), "r"(a1), "r"(a2), "r"(a3), "r"(b0), "r"(b1));
}
__device__ __forceinline__ uint32_t pack_f16(float a, float b) {
    __half2 t = __floats2half2_rn(a, b);
    return *(uint32_t*)&t;
}
__device__ __forceinline__ float2 unpack_f16(uint32_t u) {
    __half2 t = *(__half2*)&u;
    return __half22float2(t);
}
// MUFU-free exp2 (FMA/ALU pipes only). Valid for x <= ~0; err ~2e-6.
__device__ __forceinline__ float fexp2(float x) {
    x = fmaxf(x, -126.f);
    float t  = __fadd_rn(x, 12582912.f);
    int   i  = __float_as_int(t) << 23;
    float xf = x - __fsub_rn(t, 12582912.f);
    float p  = 1.3333558e-3f;
    p = fmaf(p, xf, 9.6181291e-3f);
    p = fmaf(p, xf, 5.5504109e-2f);
    p = fmaf(p, xf, 2.4022651e-1f);
    p = fmaf(p, xf, 6.9314718e-1f);
    p = fmaf(p, xf, 1.0f);
    return __int_as_float(i + __float_as_int(p));
}

// ---------------------------------------------------------------------------
// Convert kernel: fp32 [R,2048] -> fp16 [R,2048]
// ---------------------------------------------------------------------------
__global__ __launch_bounds__(256)
void conv_kernel(const float4* __restrict__ in, __half2* __restrict__ out, int nvec)
{
    int i = blockIdx.x * blockDim.x + threadIdx.x;
    if (i >= nvec) return;
    float4 v = in[i];
    out[i * 2 + 0] = __floats2half2_rn(v.x, v.y);
    out[i * 2 + 1] = __floats2half2_rn(v.z, v.w);
}

// ---------------------------------------------------------------------------
// fp16 HMMA GEMM: C = A[M,2048] @ B[N,2048]^T + bias
// K-chunk 64, 3 stages, fragment double buffering. CTA 128x256, 8 warps.
//   QKV_EPI=0: fp32 + bias -> C
//   QKV_EPI=1: per-head fp16 into H (hi always; lo only for sel==0 i.e. Q)
// ---------------------------------------------------------------------------
#define NCHUNK  (KGE / 64)         // 32
#define GSTAGES 3
#define ROWB    144
#define A_BYTES (128 * ROWB)
#define B_BYTES (256 * ROWB)
#define STAGE_B (A_BYTES + B_BYTES)
#define GEMM_SMEM (GSTAGES * STAGE_B)   // 165888

template<int QKV_EPI>
__global__ __launch_bounds__(256, 1)
void gemm_mma_kernel(const __half* __restrict__ A,
                     const __half* __restrict__ B,
                     const float* __restrict__ bias,
                     float* __restrict__ C,
                     __half* __restrict__ H,
                     int N)
{
    extern __shared__ __align__(128) char smem[];
    const uint32_t sb = smem_u32(smem);

    const int tid  = threadIdx.x;
    const int wid  = tid >> 5;
    const int lane = tid & 31;
    const int wm   = wid & 1;
    const int wn   = wid >> 1;
    const int m0   = blockIdx.y * 128;
    const int n0   = blockIdx.x * 256;

    const int a_row = (lane & 7) + ((lane >> 3) & 1) * 8;
    const int a_k8  = (lane >> 4) & 1;
    const int b_nrw = (lane & 7) + ((lane >> 4) & 1) * 8;
    const int b_k8  = (lane >> 3) & 1;

    float acc[4][8][4];
#pragma unroll
    for (int i = 0; i < 4; ++i)
#pragma unroll
        for (int j = 0; j < 8; ++j)
#pragma unroll
            for (int q = 0; q < 4; ++q) acc[i][j][q] = 0.f;

    auto load_stage = [&](int slot, int kk) {
        const uint32_t sa  = sb + slot * STAGE_B;
        const uint32_t sbb = sa + A_BYTES;
        const __half* Ak = A + (size_t)m0 * KGE + kk * 64;
        const __half* Bk = B + (size_t)n0 * KGE + kk * 64;
#pragma unroll
        for (int i = 0; i < 4; ++i) {
            int idx = tid + i * 256;
            int r = idx >> 3, c = idx & 7;
            cp16(sa + r * ROWB + c * 16, Ak + (size_t)r * KGE + c * 8);
        }
#pragma unroll
        for (int i = 0; i < 8; ++i) {
            int idx = tid + i * 256;
            int r = idx >> 3, c = idx & 7;
            cp16(sbb + r * ROWB + c * 16, Bk + (size_t)r * KGE + c * 8);
        }
    };

    load_stage(0, 0); cp_commit();
    load_stage(1, 1); cp_commit();

    uint32_t af[2][4][4];
    uint32_t bfr[2][8][2];

    for (int k = 0; k < NCHUNK; ++k) {
        const int s = k % GSTAGES;
        cp_wait<1>();
        __syncthreads();

        if (k + 2 < NCHUNK) load_stage((k + 2) % GSTAGES, k + 2);
        cp_commit();

        const uint32_t sa  = sb + s * STAGE_B + (wm * 64) * ROWB;
        const uint32_t sbb = sb + s * STAGE_B + A_BYTES + (wn * 64) * ROWB;

        auto load_frag = [&](int buf, int kkv) {
#pragma unroll
            for (int mt = 0; mt < 4; ++mt)
                ldsm_x4(af[buf][mt][0], af[buf][mt][1],
                        af[buf][mt][2], af[buf][mt][3],
                        sa + (mt * 16 + a_row) * ROWB + kkv * 32 + a_k8 * 16);
#pragma unroll
            for (int np = 0; np < 4; ++np) {
                uint32_t r0, r1, r2, r3;
                ldsm_x4(r0, r1, r2, r3,
                        sbb + (np * 16 + b_nrw) * ROWB + kkv * 32 + b_k8 * 16);
                bfr[buf][2*np][0] = r0;   bfr[buf][2*np][1] = r1;
                bfr[buf][2*np+1][0] = r2; bfr[buf][2*np+1][1] = r3;
            }
        };

        load_frag(0, 0);
#pragma unroll
        for (int kkv = 0; kkv < 4; ++kkv) {
            const int cur = kkv & 1;
            if (kkv < 3) load_frag(cur ^ 1, kkv + 1);
#pragma unroll
            for (int mt = 0; mt < 4; ++mt)
#pragma unroll
                for (int nt = 0; nt < 8; ++nt)
                    mma_f16(acc[mt][nt][0], acc[mt][nt][1],
                            acc[mt][nt][2], acc[mt][nt][3],
                            af[cur][mt][0], af[cur][mt][1],
                            af[cur][mt][2], af[cur][mt][3],
                            bfr[cur][nt][0], bfr[cur][nt][1]);
        }
    }

    const int g  = lane >> 2;
    const int ti = lane & 3;

    if (QKV_EPI == 0) {
#pragma unroll
        for (int mt = 0; mt < 4; ++mt) {
            const int row = m0 + wm * 64 + mt * 16 + g;
#pragma unroll
            for (int nt = 0; nt < 8; ++nt) {
                const int col = n0 + wn * 64 + nt * 8 + ti * 2;
                float2 bv = *(const float2*)(bias + col);
                float2 o0 = make_float2(acc[mt][nt][0] + bv.x, acc[mt][nt][1] + bv.y);
                float2 o1 = make_float2(acc[mt][nt][2] + bv.x, acc[mt][nt][3] + bv.y);
                *(float2*)(C + (size_t)row * N + col)       = o0;
                *(float2*)(C + (size_t)(row + 8) * N + col) = o1;
            }
        }
    } else {
#pragma unroll
        for (int mt = 0; mt < 4; ++mt) {
            const int row = m0 + wm * 64 + mt * 16 + g;
            const int b   = row >> 11;
            const int sidx = row & 2047;
#pragma unroll
            for (int nt = 0; nt < 8; ++nt) {
                const int col = n0 + wn * 64 + nt * 8 + ti * 2;
                const int sel = col >> 11;
                const int hh  = (col >> 7) & 15;
                const int d   = col & 127;
                float2 bv = *(const float2*)(bias + col);
                size_t base = ((((size_t)sel * BATCH + b) * NH + hh) * SEQ + sidx) * 256 + d;
#pragma unroll
                for (int half = 0; half < 2; ++half) {
                    float v0 = acc[mt][nt][half * 2 + 0] + bv.x;
                    float v1 = acc[mt][nt][half * 2 + 1] + bv.y;
                    __half h0 = __float2half_rn(v0);
                    __half h1 = __float2half_rn(v1);
                    size_t bb = base + (size_t)half * 8 * 256;
                    *(__half2*)(H + bb) = __halves2half2(h0, h1);
                    if (sel == 0) {  // lo needed only for Q
                        __half l0 = __float2half_rn(v0 - __half2float(h0));
                        __half l1 = __float2half_rn(v1 - __half2float(h1));
                        *(__half2*)(H + bb + 128) = __halves2half2(l0, l1);
                    }
                }
            }
        }
    }
}

// ---------------------------------------------------------------------------
// Flash attention, fp16 HMMA, 2-term Q and P, causal, MUFU-free softmax.
// Bq=128 (8 warps x 16 rows), Bk=64, D=128. S = (Qh+Ql)Kh; O = (Ph+Pl)Vh.
// Epilogue writes plain fp16 into g_ab [8192,2048] for the dense GEMM.
// ---------------------------------------------------------------------------
#define FROWB 272
#define FTILE (64 * FROWB)
#define FSTAGE (2 * FTILE)              // Kh + Vh
#define FLASH_SMEM (2 * FSTAGE)         // 69632

__global__ __launch_bounds__(256, 1)
void flash_mma_kernel(const __half* __restrict__ gs,
                      __half* __restrict__ Aout)
{
    extern __shared__ __align__(128) char smem[];
    const uint32_t sb = smem_u32(smem);

    const int bid = blockIdx.x;
    const int qt  = 15 - (bid >> 6);
    const int sub = bid & 63;
    const int h   = sub & 15;
    const int b   = sub >> 4;
    const int q0  = qt * 128;
    const int nkt = 2 * qt + 2;

    const int tid  = threadIdx.x;
    const int w    = tid >> 5;
    const int lane = tid & 31;
    const int g    = lane >> 2;
    const int ti   = lane & 3;
    const float scl2 = 0.08838834764831845f * 1.4426950408889634f;

    const __half* gq = gs + (((size_t)0 * BATCH + b) * NH + h) * SEQ * 256;
    const __half* gk = gs + (((size_t)1 * BATCH + b) * NH + h) * SEQ * 256;
    const __half* gv = gs + (((size_t)2 * BATCH + b) * NH + h) * SEQ * 256;

    // ---- stage Q (hi+lo) through smem ----
    {
#pragma unroll
        for (int i = 0; i < 16; ++i) {
            int idx = tid + i * 256;
            int r = idx >> 5;
            int rem = idx & 31;
            int part = rem >> 4;
            int c = rem & 15;
            cp16(sb + part * (128 * FROWB) + r * FROWB + c * 16,
                 gq + ((size_t)(q0 + r)) * 256 + part * 128 + c * 8);
        }
        cp_commit();
        cp_wait<0>();
        __syncthreads();
    }

    uint32_t qh[8][4], qlr[8][4];
    {
        int r  = w * 16 + (lane & 15);
        int cb = ((lane >> 4) & 1) * 16;
#pragma unroll
        for (int c = 0; c < 8; ++c) {
            ldsm_x4(qh[c][0], qh[c][1], qh[c][2], qh[c][3],
                    sb + r * FROWB + c * 32 + cb);
            ldsm_x4(qlr[c][0], qlr[c][1], qlr[c][2], qlr[c][3],
                    sb + 128 * FROWB + r * FROWB + c * 32 + cb);
        }
    }
    __syncthreads();

    auto load_kv = [&](int slot, int kt) {
        const uint32_t st = sb + slot * FSTAGE;
        const int k0 = kt * 64;
#pragma unroll
        for (int i = 0; i < 8; ++i) {
            int idx = tid + i * 256;
            int tile = idx >> 10;
            int rem = idx & 1023;
            int r = rem >> 4;
            int c = rem & 15;
            const __half* src = (tile == 0 ? gk : gv)
                              + ((size_t)(k0 + r)) * 256 + c * 8;
            cp16(st + tile * FTILE + r * FROWB + c * 16, src);
        }
    };

    load_kv(0, 0); cp_commit();
    load_kv(1, 1); cp_commit();

    float m_g = -1e30f, m_g8 = -1e30f, l_g = 0.f, l_g8 = 0.f;
    float o[16][4];
#pragma unroll
    for (int t = 0; t < 16; ++t)
#pragma unroll
        for (int q = 0; q < 4; ++q) o[t][q] = 0.f;

    const int b_row = (lane & 7) + ((lane >> 4) & 1) * 8;
    const int b_k   = ((lane >> 3) & 1) * 16;
    const int v_row = (lane & 7) + ((lane >> 3) & 1) * 8;
    const int v_cb  = ((lane >> 4) & 1) * 16;
    const int row_g = q0 + w * 16 + g;

    for (int kt = 0; kt < nkt; ++kt) {
        const int s = kt & 1;
        const int k0 = kt * 64;
        cp_wait<1>();
        __syncthreads();

        if (k0 <= q0 + w * 16 + 15) {
            const uint32_t sKh = sb + s * FSTAGE;
            const uint32_t sVh = sKh + FTILE;

            float s4[8][4];
#pragma unroll
            for (int j = 0; j < 8; ++j)
#pragma unroll
                for (int q = 0; q < 4; ++q) s4[j][q] = 0.f;

#pragma unroll
            for (int c8 = 0; c8 < 8; ++c8) {
                uint32_t bb[8][2];
#pragma unroll
                for (int np = 0; np < 4; ++np) {
                    uint32_t r0, r1, r2, r3;
                    ldsm_x4(r0, r1, r2, r3,
                            sKh + (np * 16 + b_row) * FROWB + c8 * 32 + b_k);
                    bb[2*np][0] = r0; bb[2*np][1] = r1;
                    bb[2*np+1][0] = r2; bb[2*np+1][1] = r3;
                }
#pragma unroll
                for (int j = 0; j < 8; ++j)
                    mma_f16(s4[j][0], s4[j][1], s4[j][2], s4[j][3],
                            qh[c8][0], qh[c8][1], qh[c8][2], qh[c8][3],
                            bb[j][0], bb[j][1]);
#pragma unroll
                for (int j = 0; j < 8; ++j)
                    mma_f16(s4[j][0], s4[j][1], s4[j][2], s4[j][3],
                            qlr[c8][0], qlr[c8][1], qlr[c8][2], qlr[c8][3],
                            bb[j][0], bb[j][1]);
            }

            const bool diag = (k0 + 63 > q0 + w * 16);
#pragma unroll
            for (int j = 0; j < 8; ++j) {
                int col = k0 + j * 8 + 2 * ti;
                s4[j][0] *= scl2; s4[j][1] *= scl2;
                s4[j][2] *= scl2; s4[j][3] *= scl2;
                if (diag) {
                    if (col     > row_g)     s4[j][0] = -1e30f;
                    if (col + 1 > row_g)     s4[j][1] = -1e30f;
                    if (col     > row_g + 8) s4[j][2] = -1e30f;
                    if (col + 1 > row_g + 8) s4[j][3] = -1e30f;
                }
            }

            float tm_g = -1e30f, tm_g8 = -1e30f;
#pragma unroll
            for (int j = 0; j < 8; ++j) {
                tm_g  = fmaxf(tm_g,  fmaxf(s4[j][0], s4[j][1]));
                tm_g8 = fmaxf(tm_g8, fmaxf(s4[j][2], s4[j][3]));
            }
            tm_g  = fmaxf(tm_g,  __shfl_xor_sync(0xffffffffu, tm_g, 1));
            tm_g  = fmaxf(tm_g,  __shfl_xor_sync(0xffffffffu, tm_g, 2));
            tm_g8 = fmaxf(tm_g8, __shfl_xor_sync(0xffffffffu, tm_g8, 1));
            tm_g8 = fmaxf(tm_g8, __shfl_xor_sync(0xffffffffu, tm_g8, 2));

            float mn_g  = fmaxf(m_g,  tm_g);
            float mn_g8 = fmaxf(m_g8, tm_g8);
            float corr_g  = fexp2(m_g  - mn_g);
            float corr_g8 = fexp2(m_g8 - mn_g8);

            float sum_g = 0.f, sum_g8 = 0.f;
#pragma unroll
            for (int j = 0; j < 8; ++j) {
                s4[j][0] = fexp2(s4[j][0] - mn_g);
                s4[j][1] = fexp2(s4[j][1] - mn_g);
                s4[j][2] = fexp2(s4[j][2] - mn_g8);
                s4[j][3] = fexp2(s4[j][3] - mn_g8);
                sum_g  += s4[j][0] + s4[j][1];
                sum_g8 += s4[j][2] + s4[j][3];
            }
            sum_g  += __shfl_xor_sync(0xffffffffu, sum_g, 1);
            sum_g  += __shfl_xor_sync(0xffffffffu, sum_g, 2);
            sum_g8 += __shfl_xor_sync(0xffffffffu, sum_g8, 1);
            sum_g8 += __shfl_xor_sync(0xffffffffu, sum_g8, 2);

            l_g  = l_g  * corr_g  + sum_g;   m_g  = mn_g;
            l_g8 = l_g8 * corr_g8 + sum_g8;  m_g8 = mn_g8;

#pragma unroll
            for (int t = 0; t < 16; ++t) {
                o[t][0] *= corr_g;  o[t][1] *= corr_g;
                o[t][2] *= corr_g8; o[t][3] *= corr_g8;
            }

#pragma unroll
            for (int c = 0; c < 4; ++c) {
                uint32_t aPh[4], aPl[4];
                aPh[0] = pack_f16(s4[2*c][0],   s4[2*c][1]);
                aPh[1] = pack_f16(s4[2*c][2],   s4[2*c][3]);
                aPh[2] = pack_f16(s4[2*c+1][0], s4[2*c+1][1]);
                aPh[3] = pack_f16(s4[2*c+1][2], s4[2*c+1][3]);
                {
                    float2 u;
                    u = unpack_f16(aPh[0]);
                    aPl[0] = pack_f16(s4[2*c][0] - u.x,   s4[2*c][1] - u.y);
                    u = unpack_f16(aPh[1]);
                    aPl[1] = pack_f16(s4[2*c][2] - u.x,   s4[2*c][3] - u.y);
                    u = unpack_f16(aPh[2]);
                    aPl[2] = pack_f16(s4[2*c+1][0] - u.x, s4[2*c+1][1] - u.y);
                    u = unpack_f16(aPh[3]);
                    aPl[3] = pack_f16(s4[2*c+1][2] - u.x, s4[2*c+1][3] - u.y);
                }
#pragma unroll
                for (int dh = 0; dh < 2; ++dh) {
                    uint32_t bv[8][2];
#pragma unroll
                    for (int dd = 0; dd < 4; ++dd) {
                        uint32_t r0, r1, r2, r3;
                        ldsm_x4_t(r0, r1, r2, r3,
                                  sVh + (c * 16 + v_row) * FROWB
                                      + (dh * 4 + dd) * 32 + v_cb);
                        bv[2*dd][0] = r0; bv[2*dd][1] = r1;
                        bv[2*dd+1][0] = r2; bv[2*dd+1][1] = r3;
                    }
#pragma unroll
                    for (int tt = 0; tt < 8; ++tt) {
                        int t = dh * 8 + tt;
                        mma_f16(o[t][0], o[t][1], o[t][2], o[t][3],
                                aPh[0], aPh[1], aPh[2], aPh[3],
                                bv[tt][0], bv[tt][1]);
                        mma_f16(o[t][0], o[t][1], o[t][2], o[t][3],
                                aPl[0], aPl[1], aPl[2], aPl[3],
                                bv[tt][0], bv[tt][1]);
                    }
                }
            }
        }

        __syncthreads();
        if (kt + 2 < nkt) load_kv(s, kt + 2);
        cp_commit();                  // unconditional: keeps wait<1> sound at tail
    }

    // ---- fused epilogue: normalize + plain fp16 into g_ab [8192,2048] ----
    const float inv_g  = 1.f / l_g;
    const float inv_g8 = 1.f / l_g8;
    const size_t row_i = (size_t)(b * SEQ + q0 + w * 16 + g);
    __half* a0 = Aout + row_i * KGE + h * HD;
    __half* a8 = a0 + (size_t)8 * KGE;
#pragma unroll
    for (int t = 0; t < 16; ++t) {
        int d = t * 8 + 2 * ti;
        *(__half2*)(a0 + d) = __floats2half2_rn(o[t][0] * inv_g, o[t][1] * inv_g);
        *(__half2*)(a8 + d) = __floats2half2_rn(o[t][2] * inv_g8, o[t][3] * inv_g8);
    }
}

// ---------------------------------------------------------------------------
// Host side
// ---------------------------------------------------------------------------
extern "C" void kernel_launch(void* const* d_in, const int* in_sizes, int n_in,
                              void* d_out, int out_size)
{
    (void)in_sizes; (void)n_in; (void)out_size;
    const float* hs      = (const float*)d_in[0];
    const float* w_qkv   = (const float*)d_in[1];
    const float* b_qkv   = (const float*)d_in[2];
    const float* w_dense = (const float*)d_in[3];
    const float* b_dense = (const float*)d_in[4];
    float* out = (float*)d_out;

    void *p_ab, *p_bqkv, *p_bdense, *p_hs;
    cudaGetSymbolAddress(&p_ab, g_ab);
    cudaGetSymbolAddress(&p_bqkv, g_bqkv);
    cudaGetSymbolAddress(&p_bdense, g_bdense);
    cudaGetSymbolAddress(&p_hs, g_hsplit);

    static bool attr_done = false;
    if (!attr_done) {
        cudaFuncSetAttribute(gemm_mma_kernel<0>,
                             cudaFuncAttributeMaxDynamicSharedMemorySize, GEMM_SMEM);
        cudaFuncSetAttribute(gemm_mma_kernel<1>,
                             cudaFuncAttributeMaxDynamicSharedMemorySize, GEMM_SMEM);
        cudaFuncSetAttribute(flash_mma_kernel,
                             cudaFuncAttributeMaxDynamicSharedMemorySize, FLASH_SMEM);
        attr_done = true;
    }

    // 1) plain fp16 converts
    {
        int nv = MROWS * HID / 4;
        conv_kernel<<<(nv + 255) / 256, 256>>>((const float4*)hs,
                                               (__half2*)p_ab, nv);
        nv = QKVN * HID / 4;
        conv_kernel<<<(nv + 255) / 256, 256>>>((const float4*)w_qkv,
                                               (__half2*)p_bqkv, nv);
        nv = HID * HID / 4;
        conv_kernel<<<(nv + 255) / 256, 256>>>((const float4*)w_dense,
                                               (__half2*)p_bdense, nv);
    }

    // 2) QKV projection (K=2048), fused per-head fp16 epilogue
    {
        dim3 g(QKVN / 256, MROWS / 128);
        gemm_mma_kernel<1><<<g, 256, GEMM_SMEM>>>(
            (const __half*)p_ab, (const __half*)p_bqkv,
            b_qkv, nullptr, (__half*)p_hs, QKVN);
    }

    // 3) flash attention (fp16 HMMA), fused plain-fp16 epilogue into g_ab
    {
        flash_mma_kernel<<<1024, 256, FLASH_SMEM>>>(
            (const __half*)p_hs, (__half*)p_ab);
    }

    // 4) dense projection (K=2048)
    {
        dim3 g(HID / 256, MROWS / 128);
        gemm_mma_kernel<0><<<g, 256, GEMM_SMEM>>>(
            (const __half*)p_ab, (const __half*)p_bdense,
            b_dense, out, nullptr, HID);
    }
}